// round 1
// baseline (speedup 1.0000x reference)
#include <cuda_runtime.h>
#include <cuda_bf16.h>

#define T_TOK 2048
#define HDIM  2048
#define IDIM  2048
#define NEXP  8
#define ROWS_PAD 5120          // 4096 assignments + 8*128 padding
#define MAX_TILES 40

// ---------------- device scratch (static: no allocs allowed) ----------------
__device__ float g_act[(size_t)ROWS_PAD * IDIM];   // silu(x@w1)*(x@w3), padded rows
__device__ int   g_row_token[ROWS_PAD];
__device__ float g_row_weight[ROWS_PAD];
__device__ int   g_tok_e[2 * T_TOK];
__device__ float g_tok_w[2 * T_TOK];
__device__ int   g_counts[NEXP];
__device__ int   g_cursor[NEXP];
__device__ int   g_seg_start[NEXP];
__device__ int   g_tile_e[MAX_TILES];
__device__ int   g_tile_row[MAX_TILES];

// ---------------- reset (out is poisoned; graph replays reuse state) --------
__global__ void reset_kernel(float* __restrict__ out) {
    int idx = blockIdx.x * 256 + threadIdx.x;
    if (idx < T_TOK * HDIM) out[idx] = 0.0f;
    if (idx < ROWS_PAD) g_row_token[idx] = -1;
    if (idx < NEXP) { g_counts[idx] = 0; g_cursor[idx] = 0; }
}

// ---------------- router: logits -> top2 -> renormalized weights ------------
__global__ __launch_bounds__(256) void router_kernel(const float* __restrict__ x,
                                                     const float* __restrict__ gw) {
    int t = blockIdx.x;
    const float* xr = x + (size_t)t * HDIM;
    float acc[NEXP];
#pragma unroll
    for (int e = 0; e < NEXP; e++) acc[e] = 0.0f;
    for (int h = threadIdx.x; h < HDIM; h += 256) {
        float xv = xr[h];
#pragma unroll
        for (int e = 0; e < NEXP; e++) acc[e] = fmaf(xv, gw[e * HDIM + h], acc[e]);
    }
#pragma unroll
    for (int off = 16; off > 0; off >>= 1)
#pragma unroll
        for (int e = 0; e < NEXP; e++)
            acc[e] += __shfl_down_sync(0xffffffffu, acc[e], off);

    __shared__ float red[8][NEXP];
    int wid = threadIdx.x >> 5, lane = threadIdx.x & 31;
    if (lane == 0)
#pragma unroll
        for (int e = 0; e < NEXP; e++) red[wid][e] = acc[e];
    __syncthreads();

    if (threadIdx.x == 0) {
        float l[NEXP];
#pragma unroll
        for (int e = 0; e < NEXP; e++) {
            float s = 0.0f;
#pragma unroll
            for (int w = 0; w < 8; w++) s += red[w][e];
            l[e] = s;
        }
        // top-2, ties -> lowest index first (matches jax top_k)
        int i0 = 0;
#pragma unroll
        for (int e = 1; e < NEXP; e++) if (l[e] > l[i0]) i0 = e;
        int i1 = -1;
#pragma unroll
        for (int e = 0; e < NEXP; e++)
            if (e != i0 && (i1 < 0 || l[e] > l[i1])) i1 = e;
        // renormalized softmax over the two selected logits
        float w0 = 1.0f / (1.0f + expf(l[i1] - l[i0]));
        float w1 = 1.0f - w0;
        g_tok_e[2 * t] = i0;     g_tok_e[2 * t + 1] = i1;
        g_tok_w[2 * t] = w0;     g_tok_w[2 * t + 1] = w1;
        atomicAdd(&g_counts[i0], 1);
        atomicAdd(&g_counts[i1], 1);
    }
}

// ---------------- plan: padded segments + tile metadata ---------------------
__global__ void plan_kernel() {
    if (threadIdx.x != 0) return;
    int off = 0, tile = 0;
    for (int e = 0; e < NEXP; e++) {
        g_seg_start[e] = off;
        int n = g_counts[e];
        int nt = (n + 127) >> 7;
        for (int j = 0; j < nt; j++) { g_tile_e[tile] = e; g_tile_row[tile] = off + (j << 7); tile++; }
        off += nt << 7;
    }
    for (; tile < MAX_TILES; tile++) g_tile_e[tile] = -1;
}

// ---------------- scatter: assign rows (value-deterministic) ----------------
__global__ void scatter_kernel() {
    int t = blockIdx.x * 256 + threadIdx.x;
    if (t >= T_TOK) return;
#pragma unroll
    for (int k = 0; k < 2; k++) {
        int e = g_tok_e[2 * t + k];
        int r = atomicAdd(&g_cursor[e], 1);
        int row = g_seg_start[e] + r;
        g_row_token[row] = t;
        g_row_weight[row] = g_tok_w[2 * t + k];
    }
}

// ---------------- GEMM1: act = silu(X@w1) * (X@w3), fused, gathered A ------
// tile 128(M) x 64(N) x 16(K); 256 threads; per-thread 8x4 for BOTH G and U.
__global__ __launch_bounds__(256) void gemm1_kernel(const float* __restrict__ x,
                                                    const float* __restrict__ w1,
                                                    const float* __restrict__ w3) {
    int tile = blockIdx.y;
    int e = g_tile_e[tile];
    if (e < 0) return;
    int row_start = g_tile_row[tile];
    int n0 = blockIdx.x * 64;

    __shared__ float As[16][128];
    __shared__ float B1s[16][64];
    __shared__ float B3s[16][64];

    int tid = threadIdx.x;
    int tx = tid & 15;           // N dir (4 cols each)
    int ty = tid >> 4;           // M dir (8 rows each)

    int a_row = tid >> 1;        // 0..127
    int a_k   = (tid & 1) << 3;  // 0 or 8
    int tok = g_row_token[row_start + a_row];
    const float* a_src = (tok >= 0) ? (x + (size_t)tok * HDIM + a_k) : (const float*)0;

    int b_k = tid >> 4;          // 0..15
    int b_n = (tid & 15) << 2;   // 0..60
    const float* b1_src = w1 + (size_t)e * HDIM * IDIM + (size_t)b_k * IDIM + n0 + b_n;
    const float* b3_src = w3 + (size_t)e * HDIM * IDIM + (size_t)b_k * IDIM + n0 + b_n;

    float accG[8][4], accU[8][4];
#pragma unroll
    for (int i = 0; i < 8; i++)
#pragma unroll
        for (int j = 0; j < 4; j++) { accG[i][j] = 0.0f; accU[i][j] = 0.0f; }

    for (int k0 = 0; k0 < HDIM; k0 += 16) {
        float4 va0 = make_float4(0.f, 0.f, 0.f, 0.f);
        float4 va1 = make_float4(0.f, 0.f, 0.f, 0.f);
        if (a_src) {
            va0 = *(const float4*)(a_src + k0);
            va1 = *(const float4*)(a_src + k0 + 4);
        }
        float4 vb1 = *(const float4*)(b1_src + (size_t)k0 * IDIM);
        float4 vb3 = *(const float4*)(b3_src + (size_t)k0 * IDIM);
        As[a_k + 0][a_row] = va0.x; As[a_k + 1][a_row] = va0.y;
        As[a_k + 2][a_row] = va0.z; As[a_k + 3][a_row] = va0.w;
        As[a_k + 4][a_row] = va1.x; As[a_k + 5][a_row] = va1.y;
        As[a_k + 6][a_row] = va1.z; As[a_k + 7][a_row] = va1.w;
        *(float4*)&B1s[b_k][b_n] = vb1;
        *(float4*)&B3s[b_k][b_n] = vb3;
        __syncthreads();
#pragma unroll
        for (int kk = 0; kk < 16; kk++) {
            float a[8];
#pragma unroll
            for (int i = 0; i < 8; i++) a[i] = As[kk][ty * 8 + i];
            float b1v[4], b3v[4];
#pragma unroll
            for (int j = 0; j < 4; j++) { b1v[j] = B1s[kk][tx * 4 + j]; b3v[j] = B3s[kk][tx * 4 + j]; }
#pragma unroll
            for (int i = 0; i < 8; i++)
#pragma unroll
                for (int j = 0; j < 4; j++) {
                    accG[i][j] = fmaf(a[i], b1v[j], accG[i][j]);
                    accU[i][j] = fmaf(a[i], b3v[j], accU[i][j]);
                }
        }
        __syncthreads();
    }
    // epilogue: silu(G)*U -> act (padding rows produce 0 since A was zeroed)
#pragma unroll
    for (int i = 0; i < 8; i++) {
        int gr = row_start + ty * 8 + i;
        float4 o;
        float* po = (float*)&o;
#pragma unroll
        for (int j = 0; j < 4; j++) {
            float g = accG[i][j], u = accU[i][j];
            float s = g / (1.0f + __expf(-g));
            po[j] = s * u;
        }
        *(float4*)&g_act[(size_t)gr * IDIM + n0 + tx * 4] = o;
    }
}

// ---------------- GEMM2: Y = act @ w2, scaled scatter-add into out ----------
// tile 128(M) x 128(N) x 16(K); 256 threads; per-thread 8x8.
__global__ __launch_bounds__(256) void gemm2_kernel(const float* __restrict__ w2,
                                                    float* __restrict__ out) {
    int tile = blockIdx.y;
    int e = g_tile_e[tile];
    if (e < 0) return;
    int row_start = g_tile_row[tile];
    int n0 = blockIdx.x * 128;

    __shared__ float As[16][128];
    __shared__ float Bs[16][128];

    int tid = threadIdx.x;
    int tx = tid & 15;           // N dir (8 cols each)
    int ty = tid >> 4;           // M dir (8 rows each)

    int a_row = tid >> 1;
    int a_k   = (tid & 1) << 3;
    const float* a_src = g_act + (size_t)(row_start + a_row) * IDIM + a_k;

    int b_k = tid >> 4;          // 0..15
    int b_n = (tid & 15) << 2;   // 0..60 (+64 for second half)
    const float* b_src = w2 + (size_t)e * IDIM * HDIM + (size_t)b_k * HDIM + n0 + b_n;

    float acc[8][8];
#pragma unroll
    for (int i = 0; i < 8; i++)
#pragma unroll
        for (int j = 0; j < 8; j++) acc[i][j] = 0.0f;

    for (int k0 = 0; k0 < IDIM; k0 += 16) {
        float4 va0 = *(const float4*)(a_src + k0);
        float4 va1 = *(const float4*)(a_src + k0 + 4);
        float4 vb0 = *(const float4*)(b_src + (size_t)k0 * HDIM);
        float4 vb1 = *(const float4*)(b_src + (size_t)k0 * HDIM + 64);
        As[a_k + 0][a_row] = va0.x; As[a_k + 1][a_row] = va0.y;
        As[a_k + 2][a_row] = va0.z; As[a_k + 3][a_row] = va0.w;
        As[a_k + 4][a_row] = va1.x; As[a_k + 5][a_row] = va1.y;
        As[a_k + 6][a_row] = va1.z; As[a_k + 7][a_row] = va1.w;
        *(float4*)&Bs[b_k][b_n]      = vb0;
        *(float4*)&Bs[b_k][b_n + 64] = vb1;
        __syncthreads();
#pragma unroll
        for (int kk = 0; kk < 16; kk++) {
            float a[8], b[8];
#pragma unroll
            for (int i = 0; i < 8; i++) a[i] = As[kk][ty * 8 + i];
#pragma unroll
            for (int j = 0; j < 8; j++) b[j] = Bs[kk][tx * 8 + j];
#pragma unroll
            for (int i = 0; i < 8; i++)
#pragma unroll
                for (int j = 0; j < 8; j++)
                    acc[i][j] = fmaf(a[i], b[j], acc[i][j]);
        }
        __syncthreads();
    }
    // epilogue: exactly 2 atomic adds per output element -> deterministic
#pragma unroll
    for (int i = 0; i < 8; i++) {
        int gr = row_start + ty * 8 + i;
        int tok = g_row_token[gr];
        if (tok < 0) continue;
        float w = g_row_weight[gr];
        float* orow = out + (size_t)tok * HDIM + n0 + tx * 8;
#pragma unroll
        for (int j = 0; j < 8; j++)
            atomicAdd(&orow[j], w * acc[i][j]);
    }
}

// ---------------- launch ----------------------------------------------------
extern "C" void kernel_launch(void* const* d_in, const int* in_sizes, int n_in,
                              void* d_out, int out_size) {
    const float* x  = (const float*)d_in[0];
    const float* gw = (const float*)d_in[1];
    const float* w1 = (const float*)d_in[2];
    const float* w3 = (const float*)d_in[3];
    const float* w2 = (const float*)d_in[4];
    float* out = (float*)d_out;

    reset_kernel<<<(T_TOK * HDIM + 255) / 256, 256>>>(out);
    router_kernel<<<T_TOK, 256>>>(x, gw);
    plan_kernel<<<1, 32>>>();
    scatter_kernel<<<(T_TOK + 255) / 256, 256>>>();

    dim3 g1(IDIM / 64, MAX_TILES);
    gemm1_kernel<<<g1, 256>>>(x, w1, w3);

    dim3 g2(HDIM / 128, MAX_TILES);
    gemm2_kernel<<<g2, 256>>>(w2, out);
}

// round 2
// speedup vs baseline: 1.0011x; 1.0011x over previous
#include <cuda_runtime.h>
#include <cuda_bf16.h>

#define T_TOK 2048
#define HDIM  2048
#define IDIM  2048
#define NEXP  8
#define ROWS_PAD 5120          // 4096 assignments + 8*128 padding
#define MAX_TILES 40

// ---------------- device scratch (static: no allocs allowed) ----------------
__device__ float g_act[(size_t)ROWS_PAD * IDIM];   // silu(x@w1)*(x@w3), padded rows
__device__ int   g_row_token[ROWS_PAD];
__device__ float g_row_weight[ROWS_PAD];
__device__ int   g_tok_e[2 * T_TOK];
__device__ float g_tok_w[2 * T_TOK];
__device__ int   g_counts[NEXP];
__device__ int   g_cursor[NEXP];
__device__ int   g_seg_start[NEXP];
__device__ int   g_tile_e[MAX_TILES];
__device__ int   g_tile_row[MAX_TILES];

// ---------------- reset (out is poisoned; graph replays reuse state) --------
__global__ void reset_kernel(float* __restrict__ out) {
    int idx = blockIdx.x * 256 + threadIdx.x;
    if (idx < T_TOK * HDIM) out[idx] = 0.0f;
    if (idx < ROWS_PAD) g_row_token[idx] = -1;
    if (idx < NEXP) { g_counts[idx] = 0; g_cursor[idx] = 0; }
}

// ---------------- router: logits -> top2 -> renormalized weights ------------
__global__ __launch_bounds__(256) void router_kernel(const float* __restrict__ x,
                                                     const float* __restrict__ gw) {
    int t = blockIdx.x;
    const float* xr = x + (size_t)t * HDIM;
    float acc[NEXP];
#pragma unroll
    for (int e = 0; e < NEXP; e++) acc[e] = 0.0f;
    for (int h = threadIdx.x; h < HDIM; h += 256) {
        float xv = xr[h];
#pragma unroll
        for (int e = 0; e < NEXP; e++) acc[e] = fmaf(xv, gw[e * HDIM + h], acc[e]);
    }
#pragma unroll
    for (int off = 16; off > 0; off >>= 1)
#pragma unroll
        for (int e = 0; e < NEXP; e++)
            acc[e] += __shfl_down_sync(0xffffffffu, acc[e], off);

    __shared__ float red[8][NEXP];
    int wid = threadIdx.x >> 5, lane = threadIdx.x & 31;
    if (lane == 0)
#pragma unroll
        for (int e = 0; e < NEXP; e++) red[wid][e] = acc[e];
    __syncthreads();

    if (threadIdx.x == 0) {
        float l[NEXP];
#pragma unroll
        for (int e = 0; e < NEXP; e++) {
            float s = 0.0f;
#pragma unroll
            for (int w = 0; w < 8; w++) s += red[w][e];
            l[e] = s;
        }
        // top-2, ties -> lowest index first (matches jax top_k)
        int i0 = 0;
#pragma unroll
        for (int e = 1; e < NEXP; e++) if (l[e] > l[i0]) i0 = e;
        int i1 = -1;
#pragma unroll
        for (int e = 0; e < NEXP; e++)
            if (e != i0 && (i1 < 0 || l[e] > l[i1])) i1 = e;
        // renormalized softmax over the two selected logits
        float w0 = 1.0f / (1.0f + expf(l[i1] - l[i0]));
        float w1 = 1.0f - w0;
        g_tok_e[2 * t] = i0;     g_tok_e[2 * t + 1] = i1;
        g_tok_w[2 * t] = w0;     g_tok_w[2 * t + 1] = w1;
        atomicAdd(&g_counts[i0], 1);
        atomicAdd(&g_counts[i1], 1);
    }
}

// ---------------- plan: padded segments + tile metadata ---------------------
__global__ void plan_kernel() {
    if (threadIdx.x != 0) return;
    int off = 0, tile = 0;
    for (int e = 0; e < NEXP; e++) {
        g_seg_start[e] = off;
        int n = g_counts[e];
        int nt = (n + 127) >> 7;
        for (int j = 0; j < nt; j++) { g_tile_e[tile] = e; g_tile_row[tile] = off + (j << 7); tile++; }
        off += nt << 7;
    }
    for (; tile < MAX_TILES; tile++) g_tile_e[tile] = -1;
}

// ---------------- scatter: assign rows (value-deterministic) ----------------
__global__ void scatter_kernel() {
    int t = blockIdx.x * 256 + threadIdx.x;
    if (t >= T_TOK) return;
#pragma unroll
    for (int k = 0; k < 2; k++) {
        int e = g_tok_e[2 * t + k];
        int r = atomicAdd(&g_cursor[e], 1);
        int row = g_seg_start[e] + r;
        g_row_token[row] = t;
        g_row_weight[row] = g_tok_w[2 * t + k];
    }
}

// ---------------- GEMM1: act = silu(X@w1) * (X@w3), fused, gathered A ------
// tile 128(M) x 64(N) x 16(K); 256 threads; per-thread 8x4 for BOTH G and U.
__global__ __launch_bounds__(256) void gemm1_kernel(const float* __restrict__ x,
                                                    const float* __restrict__ w1,
                                                    const float* __restrict__ w3) {
    int tile = blockIdx.y;
    int e = g_tile_e[tile];
    if (e < 0) return;
    int row_start = g_tile_row[tile];
    int n0 = blockIdx.x * 64;

    __shared__ float As[16][128];
    __shared__ float B1s[16][64];
    __shared__ float B3s[16][64];

    int tid = threadIdx.x;
    int tx = tid & 15;           // N dir (4 cols each)
    int ty = tid >> 4;           // M dir (8 rows each)

    int a_row = tid >> 1;        // 0..127
    int a_k   = (tid & 1) << 3;  // 0 or 8
    int tok = g_row_token[row_start + a_row];
    const float* a_src = (tok >= 0) ? (x + (size_t)tok * HDIM + a_k) : (const float*)0;

    int b_k = tid >> 4;          // 0..15
    int b_n = (tid & 15) << 2;   // 0..60
    const float* b1_src = w1 + (size_t)e * HDIM * IDIM + (size_t)b_k * IDIM + n0 + b_n;
    const float* b3_src = w3 + (size_t)e * HDIM * IDIM + (size_t)b_k * IDIM + n0 + b_n;

    float accG[8][4], accU[8][4];
#pragma unroll
    for (int i = 0; i < 8; i++)
#pragma unroll
        for (int j = 0; j < 4; j++) { accG[i][j] = 0.0f; accU[i][j] = 0.0f; }

    for (int k0 = 0; k0 < HDIM; k0 += 16) {
        float4 va0 = make_float4(0.f, 0.f, 0.f, 0.f);
        float4 va1 = make_float4(0.f, 0.f, 0.f, 0.f);
        if (a_src) {
            va0 = *(const float4*)(a_src + k0);
            va1 = *(const float4*)(a_src + k0 + 4);
        }
        float4 vb1 = *(const float4*)(b1_src + (size_t)k0 * IDIM);
        float4 vb3 = *(const float4*)(b3_src + (size_t)k0 * IDIM);
        As[a_k + 0][a_row] = va0.x; As[a_k + 1][a_row] = va0.y;
        As[a_k + 2][a_row] = va0.z; As[a_k + 3][a_row] = va0.w;
        As[a_k + 4][a_row] = va1.x; As[a_k + 5][a_row] = va1.y;
        As[a_k + 6][a_row] = va1.z; As[a_k + 7][a_row] = va1.w;
        *(float4*)&B1s[b_k][b_n] = vb1;
        *(float4*)&B3s[b_k][b_n] = vb3;
        __syncthreads();
#pragma unroll
        for (int kk = 0; kk < 16; kk++) {
            float a[8];
#pragma unroll
            for (int i = 0; i < 8; i++) a[i] = As[kk][ty * 8 + i];
            float b1v[4], b3v[4];
#pragma unroll
            for (int j = 0; j < 4; j++) { b1v[j] = B1s[kk][tx * 4 + j]; b3v[j] = B3s[kk][tx * 4 + j]; }
#pragma unroll
            for (int i = 0; i < 8; i++)
#pragma unroll
                for (int j = 0; j < 4; j++) {
                    accG[i][j] = fmaf(a[i], b1v[j], accG[i][j]);
                    accU[i][j] = fmaf(a[i], b3v[j], accU[i][j]);
                }
        }
        __syncthreads();
    }
    // epilogue: silu(G)*U -> act (padding rows produce 0 since A was zeroed)
#pragma unroll
    for (int i = 0; i < 8; i++) {
        int gr = row_start + ty * 8 + i;
        float4 o;
        float* po = (float*)&o;
#pragma unroll
        for (int j = 0; j < 4; j++) {
            float g = accG[i][j], u = accU[i][j];
            float s = g / (1.0f + __expf(-g));
            po[j] = s * u;
        }
        *(float4*)&g_act[(size_t)gr * IDIM + n0 + tx * 4] = o;
    }
}

// ---------------- GEMM2: Y = act @ w2, scaled scatter-add into out ----------
// tile 128(M) x 128(N) x 16(K); 256 threads; per-thread 8x8.
__global__ __launch_bounds__(256) void gemm2_kernel(const float* __restrict__ w2,
                                                    float* __restrict__ out) {
    int tile = blockIdx.y;
    int e = g_tile_e[tile];
    if (e < 0) return;
    int row_start = g_tile_row[tile];
    int n0 = blockIdx.x * 128;

    __shared__ float As[16][128];
    __shared__ float Bs[16][128];

    int tid = threadIdx.x;
    int tx = tid & 15;           // N dir (8 cols each)
    int ty = tid >> 4;           // M dir (8 rows each)

    int a_row = tid >> 1;
    int a_k   = (tid & 1) << 3;
    const float* a_src = g_act + (size_t)(row_start + a_row) * IDIM + a_k;

    int b_k = tid >> 4;          // 0..15
    int b_n = (tid & 15) << 2;   // 0..60 (+64 for second half)
    const float* b_src = w2 + (size_t)e * IDIM * HDIM + (size_t)b_k * HDIM + n0 + b_n;

    float acc[8][8];
#pragma unroll
    for (int i = 0; i < 8; i++)
#pragma unroll
        for (int j = 0; j < 8; j++) acc[i][j] = 0.0f;

    for (int k0 = 0; k0 < IDIM; k0 += 16) {
        float4 va0 = *(const float4*)(a_src + k0);
        float4 va1 = *(const float4*)(a_src + k0 + 4);
        float4 vb0 = *(const float4*)(b_src + (size_t)k0 * HDIM);
        float4 vb1 = *(const float4*)(b_src + (size_t)k0 * HDIM + 64);
        As[a_k + 0][a_row] = va0.x; As[a_k + 1][a_row] = va0.y;
        As[a_k + 2][a_row] = va0.z; As[a_k + 3][a_row] = va0.w;
        As[a_k + 4][a_row] = va1.x; As[a_k + 5][a_row] = va1.y;
        As[a_k + 6][a_row] = va1.z; As[a_k + 7][a_row] = va1.w;
        *(float4*)&Bs[b_k][b_n]      = vb0;
        *(float4*)&Bs[b_k][b_n + 64] = vb1;
        __syncthreads();
#pragma unroll
        for (int kk = 0; kk < 16; kk++) {
            float a[8], b[8];
#pragma unroll
            for (int i = 0; i < 8; i++) a[i] = As[kk][ty * 8 + i];
#pragma unroll
            for (int j = 0; j < 8; j++) b[j] = Bs[kk][tx * 8 + j];
#pragma unroll
            for (int i = 0; i < 8; i++)
#pragma unroll
                for (int j = 0; j < 8; j++)
                    acc[i][j] = fmaf(a[i], b[j], acc[i][j]);
        }
        __syncthreads();
    }
    // epilogue: exactly 2 atomic adds per output element -> deterministic
#pragma unroll
    for (int i = 0; i < 8; i++) {
        int gr = row_start + ty * 8 + i;
        int tok = g_row_token[gr];
        if (tok < 0) continue;
        float w = g_row_weight[gr];
        float* orow = out + (size_t)tok * HDIM + n0 + tx * 8;
#pragma unroll
        for (int j = 0; j < 8; j++)
            atomicAdd(&orow[j], w * acc[i][j]);
    }
}

// ---------------- launch ----------------------------------------------------
extern "C" void kernel_launch(void* const* d_in, const int* in_sizes, int n_in,
                              void* d_out, int out_size) {
    const float* x  = (const float*)d_in[0];
    const float* gw = (const float*)d_in[1];
    const float* w1 = (const float*)d_in[2];
    const float* w3 = (const float*)d_in[3];
    const float* w2 = (const float*)d_in[4];
    float* out = (float*)d_out;

    reset_kernel<<<(T_TOK * HDIM + 255) / 256, 256>>>(out);
    router_kernel<<<T_TOK, 256>>>(x, gw);
    plan_kernel<<<1, 32>>>();
    scatter_kernel<<<(T_TOK + 255) / 256, 256>>>();

    dim3 g1(IDIM / 64, MAX_TILES);
    gemm1_kernel<<<g1, 256>>>(x, w1, w3);

    dim3 g2(HDIM / 128, MAX_TILES);
    gemm2_kernel<<<g2, 256>>>(w2, out);
}

// round 5
// speedup vs baseline: 2.0880x; 2.0857x over previous
#include <cuda_runtime.h>
#include <cuda_bf16.h>
#include <cstdint>

#define T_TOK 2048
#define HDIM  2048
#define IDIM  2048
#define NEXP  8
#define ROWS_PAD 5120          // 40 tiles * 128
#define MAX_TILES 40
#define WMAT ((size_t)2048 * 2048)

// stage layout (bytes, both GEMMs): Ah 0..10239, Al 10240..20479, B planes at 20480+
#define APL   10240            // 128 rows * 80B (32 bf16 + 8 pad)
#define BOFF  20480
#define STAGE 36864

// ---------------- device scratch ---------------------------------------------
__device__ uint32_t g_act[(size_t)ROWS_PAD * IDIM]; // silu(g)*u packed (hi<<16|lo)
__device__ int   g_row_token[ROWS_PAD];
__device__ float g_row_weight[ROWS_PAD];
__device__ int   g_tok_e[2 * T_TOK];
__device__ float g_tok_w[2 * T_TOK];
__device__ int   g_counts[NEXP];
__device__ int   g_cursor[NEXP];
__device__ int   g_seg_start[NEXP];
__device__ int   g_tile_e[MAX_TILES];
__device__ int   g_tile_row[MAX_TILES];

// ---------------- helpers ----------------------------------------------------
__device__ __forceinline__ uint32_t smem_u32(const void* p) {
    return (uint32_t)__cvta_generic_to_shared(p);
}
__device__ __forceinline__ void mma16816(float* c, const uint32_t* a, const uint32_t* b) {
    asm volatile(
        "mma.sync.aligned.m16n8k16.row.col.f32.bf16.bf16.f32 "
        "{%0,%1,%2,%3}, {%4,%5,%6,%7}, {%8,%9}, {%0,%1,%2,%3};"
        : "+f"(c[0]), "+f"(c[1]), "+f"(c[2]), "+f"(c[3])
        : "r"(a[0]), "r"(a[1]), "r"(a[2]), "r"(a[3]), "r"(b[0]), "r"(b[1]));
}
__device__ __forceinline__ void ldsm4(uint32_t* r, uint32_t a) {
    asm volatile("ldmatrix.sync.aligned.m8n8.x4.shared.b16 {%0,%1,%2,%3}, [%4];"
        : "=r"(r[0]), "=r"(r[1]), "=r"(r[2]), "=r"(r[3]) : "r"(a));
}
__device__ __forceinline__ void ldsm4t(uint32_t* r, uint32_t a) {
    asm volatile("ldmatrix.sync.aligned.m8n8.x4.trans.shared.b16 {%0,%1,%2,%3}, [%4];"
        : "=r"(r[0]), "=r"(r[1]), "=r"(r[2]), "=r"(r[3]) : "r"(a));
}
__device__ __forceinline__ void sts4(uint32_t a, uint32_t v0, uint32_t v1, uint32_t v2, uint32_t v3) {
    asm volatile("st.shared.v4.b32 [%0], {%1,%2,%3,%4};" :: "r"(a), "r"(v0), "r"(v1), "r"(v2), "r"(v3) : "memory");
}
__device__ __forceinline__ uint32_t prmt32(uint32_t a, uint32_t b, uint32_t s) {
    uint32_t r; asm("prmt.b32 %0,%1,%2,%3;" : "=r"(r) : "r"(a), "r"(b), "r"(s)); return r;
}
__device__ __forceinline__ void split2(float a, float b, uint32_t& hi, uint32_t& lo) {
    __nv_bfloat162 h = __floats2bfloat162_rn(a, b);   // .x -> low 16 bits
    float2 hf = __bfloat1622float2(h);
    __nv_bfloat162 l = __floats2bfloat162_rn(a - hf.x, b - hf.y);
    hi = *(uint32_t*)&h;
    lo = *(uint32_t*)&l;
}
__device__ __forceinline__ uint32_t packhl(float v) {
    __nv_bfloat16 h = __float2bfloat16(v);
    float r = v - __bfloat162float(h);
    __nv_bfloat16 l = __float2bfloat16(r);
    return ((uint32_t)__bfloat16_as_ushort(h) << 16) | (uint32_t)__bfloat16_as_ushort(l);
}

// ---------------- reset ------------------------------------------------------
__global__ void reset_kernel(float* __restrict__ out) {
    int idx = blockIdx.x * 256 + threadIdx.x;
    if (idx < T_TOK * HDIM) out[idx] = 0.0f;
    if (idx < ROWS_PAD) g_row_token[idx] = -1;
    if (idx < NEXP) { g_counts[idx] = 0; g_cursor[idx] = 0; }
}

// ---------------- router -----------------------------------------------------
__global__ __launch_bounds__(256) void router_kernel(const float* __restrict__ x,
                                                     const float* __restrict__ gw) {
    int t = blockIdx.x;
    const float* xr = x + (size_t)t * HDIM;
    float acc[NEXP];
#pragma unroll
    for (int e = 0; e < NEXP; e++) acc[e] = 0.0f;
    for (int h = threadIdx.x; h < HDIM; h += 256) {
        float xv = xr[h];
#pragma unroll
        for (int e = 0; e < NEXP; e++) acc[e] = fmaf(xv, gw[e * HDIM + h], acc[e]);
    }
#pragma unroll
    for (int off = 16; off > 0; off >>= 1)
#pragma unroll
        for (int e = 0; e < NEXP; e++)
            acc[e] += __shfl_down_sync(0xffffffffu, acc[e], off);

    __shared__ float red[8][NEXP];
    int wid = threadIdx.x >> 5, lane = threadIdx.x & 31;
    if (lane == 0)
#pragma unroll
        for (int e = 0; e < NEXP; e++) red[wid][e] = acc[e];
    __syncthreads();

    if (threadIdx.x == 0) {
        float l[NEXP];
#pragma unroll
        for (int e = 0; e < NEXP; e++) {
            float s = 0.0f;
#pragma unroll
            for (int w = 0; w < 8; w++) s += red[w][e];
            l[e] = s;
        }
        int i0 = 0;
#pragma unroll
        for (int e = 1; e < NEXP; e++) if (l[e] > l[i0]) i0 = e;
        int i1 = -1;
#pragma unroll
        for (int e = 0; e < NEXP; e++)
            if (e != i0 && (i1 < 0 || l[e] > l[i1])) i1 = e;
        float w0 = 1.0f / (1.0f + expf(l[i1] - l[i0]));
        float w1 = 1.0f - w0;
        g_tok_e[2 * t] = i0;     g_tok_e[2 * t + 1] = i1;
        g_tok_w[2 * t] = w0;     g_tok_w[2 * t + 1] = w1;
        atomicAdd(&g_counts[i0], 1);
        atomicAdd(&g_counts[i1], 1);
    }
}

// ---------------- plan + scatter ---------------------------------------------
__global__ void plan_kernel() {
    if (threadIdx.x != 0) return;
    int off = 0, tile = 0;
    for (int e = 0; e < NEXP; e++) {
        g_seg_start[e] = off;
        int n = g_counts[e];
        int nt = (n + 127) >> 7;
        for (int j = 0; j < nt; j++) { g_tile_e[tile] = e; g_tile_row[tile] = off + (j << 7); tile++; }
        off += nt << 7;
    }
    for (; tile < MAX_TILES; tile++) g_tile_e[tile] = -1;
}

__global__ void scatter_kernel() {
    int t = blockIdx.x * 256 + threadIdx.x;
    if (t >= T_TOK) return;
#pragma unroll
    for (int k = 0; k < 2; k++) {
        int e = g_tok_e[2 * t + k];
        int r = atomicAdd(&g_cursor[e], 1);
        int row = g_seg_start[e] + r;
        g_row_token[row] = t;
        g_row_weight[row] = g_tok_w[2 * t + k];
    }
}

// ---------------- GEMM1: HMMA, fused gate+up + SiLU --------------------------
// CTA: M=128, N=64 (per mat), KC=32. 8 warps = 4(M) x 2(N), warp 32x32, dual acc.
__global__ __launch_bounds__(256) void gemm1_kernel(const float* __restrict__ x,
                                                    const float* __restrict__ w1,
                                                    const float* __restrict__ w3) {
    int e = g_tile_e[blockIdx.y];
    if (e < 0) return;
    int row_start = g_tile_row[blockIdx.y];
    int n0 = blockIdx.x * 64;
    extern __shared__ __align__(1024) char smem[];
    uint32_t SB = smem_u32(smem);

    const int tid = threadIdx.x;
    const int lane = tid & 31, wid = tid >> 5;
    const int wm = (wid & 3) * 32, wn = (wid >> 2) * 32;

    // staging maps
    const int bmat = tid >> 7;                  // 0:w1  1:w3
    const int bk = (tid & 127) >> 2;            // 0..31
    const int bn = (tid & 3) * 16;              // float col offset
    const float* bsrc = (bmat ? w3 : w1) + (size_t)e * WMAT + (size_t)bk * IDIM + n0 + bn;
    const int ar = tid >> 1;                    // 0..127
    const int akh = (tid & 1) * 16;
    int tok0 = g_row_token[row_start + ar];
    const float* asrc = (tok0 >= 0) ? x + (size_t)tok0 * HDIM + akh : (const float*)0;

    const uint32_t a_sts = (uint32_t)(ar * 80 + akh * 2);
    const uint32_t bswz = (uint32_t)((bk & 7) * 16);
    const uint32_t b_base = (uint32_t)(BOFF + bmat * 8192 + bk * 128);
    const uint32_t b_sts0 = b_base + (((uint32_t)(bn * 2)) ^ bswz);
    const uint32_t b_sts1 = b_base + (((uint32_t)(bn * 2 + 16)) ^ bswz);

    float4 ra[4], rb[4];
    float accG[2][4][4], accU[2][4][4];
#pragma unroll
    for (int i = 0; i < 2; i++)
#pragma unroll
        for (int j = 0; j < 4; j++)
#pragma unroll
            for (int q = 0; q < 4; q++) { accG[i][j][q] = 0.0f; accU[i][j][q] = 0.0f; }

#define G1_LDG(c) do { int k0 = (c) * 32;                                         \
        if (asrc) { ra[0] = *(const float4*)(asrc + k0);                          \
                    ra[1] = *(const float4*)(asrc + k0 + 4);                      \
                    ra[2] = *(const float4*)(asrc + k0 + 8);                      \
                    ra[3] = *(const float4*)(asrc + k0 + 12); }                   \
        else { ra[0] = make_float4(0.f,0.f,0.f,0.f); ra[1]=ra[0]; ra[2]=ra[0]; ra[3]=ra[0]; } \
        const float* bp = bsrc + (size_t)k0 * IDIM;                               \
        rb[0] = *(const float4*)(bp);      rb[1] = *(const float4*)(bp + 4);      \
        rb[2] = *(const float4*)(bp + 8);  rb[3] = *(const float4*)(bp + 12);     \
    } while (0)

#define G1_STS(stb) do {                                                          \
        uint32_t h[8], l[8];                                                      \
        split2(ra[0].x, ra[0].y, h[0], l[0]); split2(ra[0].z, ra[0].w, h[1], l[1]); \
        split2(ra[1].x, ra[1].y, h[2], l[2]); split2(ra[1].z, ra[1].w, h[3], l[3]); \
        split2(ra[2].x, ra[2].y, h[4], l[4]); split2(ra[2].z, ra[2].w, h[5], l[5]); \
        split2(ra[3].x, ra[3].y, h[6], l[6]); split2(ra[3].z, ra[3].w, h[7], l[7]); \
        sts4((stb) + a_sts,        h[0], h[1], h[2], h[3]);                       \
        sts4((stb) + a_sts + 16,   h[4], h[5], h[6], h[7]);                       \
        sts4((stb) + APL + a_sts,      l[0], l[1], l[2], l[3]);                   \
        sts4((stb) + APL + a_sts + 16, l[4], l[5], l[6], l[7]);                   \
        split2(rb[0].x, rb[0].y, h[0], l[0]); split2(rb[0].z, rb[0].w, h[1], l[1]); \
        split2(rb[1].x, rb[1].y, h[2], l[2]); split2(rb[1].z, rb[1].w, h[3], l[3]); \
        split2(rb[2].x, rb[2].y, h[4], l[4]); split2(rb[2].z, rb[2].w, h[5], l[5]); \
        split2(rb[3].x, rb[3].y, h[6], l[6]); split2(rb[3].z, rb[3].w, h[7], l[7]); \
        sts4((stb) + b_sts0,        h[0], h[1], h[2], h[3]);                      \
        sts4((stb) + b_sts1,        h[4], h[5], h[6], h[7]);                      \
        sts4((stb) + b_sts0 + 4096, l[0], l[1], l[2], l[3]);                      \
        sts4((stb) + b_sts1 + 4096, l[4], l[5], l[6], l[7]);                      \
    } while (0)

    G1_LDG(0);
    G1_STS(SB);
    __syncthreads();

    for (int c = 0; c < 64; c++) {
        uint32_t stb = SB + (uint32_t)(c & 1) * STAGE;
        if (c < 63) G1_LDG(c + 1);
#pragma unroll
        for (int s = 0; s < 2; s++) {
            uint32_t aH[2][4], aL[2][4];
#pragma unroll
            for (int i = 0; i < 2; i++) {
                uint32_t ab = stb + (uint32_t)((wm + i * 16 + (lane & 15)) * 80 +
                                               ((lane >> 4) * 16) + s * 32);
                ldsm4(aH[i], ab);
                ldsm4(aL[i], ab + APL);
            }
            int krow = s * 16 + (lane & 15);
            uint32_t ksw = (uint32_t)((krow & 7) * 16);
            uint32_t rowb = (uint32_t)(krow * 128);
            uint32_t bf[2][4][2];
#pragma unroll
            for (int m = 0; m < 2; m++)
#pragma unroll
                for (int j2 = 0; j2 < 2; j2++) {
                    uint32_t chunk = (((uint32_t)((wn + j2 * 16) * 2 + (lane >> 4) * 16)) ^ ksw);
                    uint32_t r[4];
                    ldsm4t(r, stb + BOFF + (uint32_t)m * 8192 + rowb + chunk);
                    bf[m][j2 * 2][0] = r[0]; bf[m][j2 * 2][1] = r[1];
                    bf[m][j2 * 2 + 1][0] = r[2]; bf[m][j2 * 2 + 1][1] = r[3];
                }
            // products Ah*Bh, Al*Bh
#pragma unroll
            for (int i = 0; i < 2; i++)
#pragma unroll
                for (int j = 0; j < 4; j++) {
                    mma16816(accG[i][j], aH[i], bf[0][j]);
                    mma16816(accU[i][j], aH[i], bf[1][j]);
                }
#pragma unroll
            for (int i = 0; i < 2; i++)
#pragma unroll
                for (int j = 0; j < 4; j++) {
                    mma16816(accG[i][j], aL[i], bf[0][j]);
                    mma16816(accU[i][j], aL[i], bf[1][j]);
                }
            // reload lo B planes, product Ah*Bl
#pragma unroll
            for (int m = 0; m < 2; m++)
#pragma unroll
                for (int j2 = 0; j2 < 2; j2++) {
                    uint32_t chunk = (((uint32_t)((wn + j2 * 16) * 2 + (lane >> 4) * 16)) ^ ksw);
                    uint32_t r[4];
                    ldsm4t(r, stb + BOFF + (uint32_t)m * 8192 + 4096 + rowb + chunk);
                    bf[m][j2 * 2][0] = r[0]; bf[m][j2 * 2][1] = r[1];
                    bf[m][j2 * 2 + 1][0] = r[2]; bf[m][j2 * 2 + 1][1] = r[3];
                }
#pragma unroll
            for (int i = 0; i < 2; i++)
#pragma unroll
                for (int j = 0; j < 4; j++) {
                    mma16816(accG[i][j], aH[i], bf[0][j]);
                    mma16816(accU[i][j], aH[i], bf[1][j]);
                }
        }
        if (c < 63) G1_STS(SB + (uint32_t)((c + 1) & 1) * STAGE);
        __syncthreads();
    }

    // epilogue: silu(G)*U packed hi/lo -> g_act
    int r0 = lane >> 2, cc = 2 * (lane & 3);
#pragma unroll
    for (int i = 0; i < 2; i++)
#pragma unroll
        for (int j = 0; j < 4; j++) {
            int col = n0 + wn + j * 8 + cc;
#pragma unroll
            for (int h = 0; h < 2; h++) {
                int row = row_start + wm + i * 16 + r0 + h * 8;
                float g0 = accG[i][j][2 * h],     u0 = accU[i][j][2 * h];
                float g1 = accG[i][j][2 * h + 1], u1 = accU[i][j][2 * h + 1];
                float a0 = (g0 / (1.0f + __expf(-g0))) * u0;
                float a1 = (g1 / (1.0f + __expf(-g1))) * u1;
                *(uint2*)&g_act[(size_t)row * IDIM + col] = make_uint2(packhl(a0), packhl(a1));
            }
        }
#undef G1_LDG
#undef G1_STS
}

// ---------------- GEMM2: HMMA, down proj + weighted scatter-add --------------
// CTA: M=128, N=128, KC=32. 8 warps = 2(M) x 4(N), warp 64x32.
__global__ __launch_bounds__(256) void gemm2_kernel(const float* __restrict__ w2,
                                                    float* __restrict__ out) {
    int e = g_tile_e[blockIdx.y];
    if (e < 0) return;
    int row_start = g_tile_row[blockIdx.y];
    int n0 = blockIdx.x * 128;
    extern __shared__ __align__(1024) char smem[];
    uint32_t SB = smem_u32(smem);

    const int tid = threadIdx.x;
    const int lane = tid & 31, wid = tid >> 5;
    const int wm = (wid & 1) * 64, wn = (wid >> 1) * 32;

    const int ar = tid >> 1;
    const int akh = (tid & 1) * 16;
    const uint32_t* asrc = g_act + (size_t)(row_start + ar) * IDIM + akh;
    const int bk = tid >> 3;                    // 0..31
    const int bn = (tid & 7) * 16;
    const float* bsrc = w2 + (size_t)e * WMAT + (size_t)bk * HDIM + n0 + bn;

    const uint32_t a_sts = (uint32_t)(ar * 80 + akh * 2);
    const uint32_t bswz = (uint32_t)((bk & 7) * 16);
    const uint32_t b_base = (uint32_t)(BOFF + bk * 256);
    const uint32_t b_sts0 = b_base + (((uint32_t)(bn * 2)) ^ bswz);
    const uint32_t b_sts1 = b_base + (((uint32_t)(bn * 2 + 16)) ^ bswz);

    uint4 pa[4];
    float4 rb[4];
    float acc[4][4][4];
#pragma unroll
    for (int i = 0; i < 4; i++)
#pragma unroll
        for (int j = 0; j < 4; j++)
#pragma unroll
            for (int q = 0; q < 4; q++) acc[i][j][q] = 0.0f;

#define G2_LDG(c) do { int k0 = (c) * 32;                                         \
        pa[0] = *(const uint4*)(asrc + k0);     pa[1] = *(const uint4*)(asrc + k0 + 4); \
        pa[2] = *(const uint4*)(asrc + k0 + 8); pa[3] = *(const uint4*)(asrc + k0 + 12); \
        const float* bp = bsrc + (size_t)k0 * HDIM;                               \
        rb[0] = *(const float4*)(bp);      rb[1] = *(const float4*)(bp + 4);      \
        rb[2] = *(const float4*)(bp + 8);  rb[3] = *(const float4*)(bp + 12);     \
    } while (0)

#define G2_STS(stb) do {                                                          \
        uint32_t h[8], l[8];                                                      \
        h[0] = prmt32(pa[0].x, pa[0].y, 0x7632u); l[0] = prmt32(pa[0].x, pa[0].y, 0x5410u); \
        h[1] = prmt32(pa[0].z, pa[0].w, 0x7632u); l[1] = prmt32(pa[0].z, pa[0].w, 0x5410u); \
        h[2] = prmt32(pa[1].x, pa[1].y, 0x7632u); l[2] = prmt32(pa[1].x, pa[1].y, 0x5410u); \
        h[3] = prmt32(pa[1].z, pa[1].w, 0x7632u); l[3] = prmt32(pa[1].z, pa[1].w, 0x5410u); \
        h[4] = prmt32(pa[2].x, pa[2].y, 0x7632u); l[4] = prmt32(pa[2].x, pa[2].y, 0x5410u); \
        h[5] = prmt32(pa[2].z, pa[2].w, 0x7632u); l[5] = prmt32(pa[2].z, pa[2].w, 0x5410u); \
        h[6] = prmt32(pa[3].x, pa[3].y, 0x7632u); l[6] = prmt32(pa[3].x, pa[3].y, 0x5410u); \
        h[7] = prmt32(pa[3].z, pa[3].w, 0x7632u); l[7] = prmt32(pa[3].z, pa[3].w, 0x5410u); \
        sts4((stb) + a_sts,        h[0], h[1], h[2], h[3]);                       \
        sts4((stb) + a_sts + 16,   h[4], h[5], h[6], h[7]);                       \
        sts4((stb) + APL + a_sts,      l[0], l[1], l[2], l[3]);                   \
        sts4((stb) + APL + a_sts + 16, l[4], l[5], l[6], l[7]);                   \
        split2(rb[0].x, rb[0].y, h[0], l[0]); split2(rb[0].z, rb[0].w, h[1], l[1]); \
        split2(rb[1].x, rb[1].y, h[2], l[2]); split2(rb[1].z, rb[1].w, h[3], l[3]); \
        split2(rb[2].x, rb[2].y, h[4], l[4]); split2(rb[2].z, rb[2].w, h[5], l[5]); \
        split2(rb[3].x, rb[3].y, h[6], l[6]); split2(rb[3].z, rb[3].w, h[7], l[7]); \
        sts4((stb) + b_sts0,        h[0], h[1], h[2], h[3]);                      \
        sts4((stb) + b_sts1,        h[4], h[5], h[6], h[7]);                      \
        sts4((stb) + b_sts0 + 8192, l[0], l[1], l[2], l[3]);                      \
        sts4((stb) + b_sts1 + 8192, l[4], l[5], l[6], l[7]);                      \
    } while (0)

    G2_LDG(0);
    G2_STS(SB);
    __syncthreads();

    for (int c = 0; c < 64; c++) {
        uint32_t stb = SB + (uint32_t)(c & 1) * STAGE;
        if (c < 63) G2_LDG(c + 1);
#pragma unroll
        for (int s = 0; s < 2; s++) {
            uint32_t aH[4][4], aL[4][4];
#pragma unroll
            for (int i = 0; i < 4; i++) {
                uint32_t ab = stb + (uint32_t)((wm + i * 16 + (lane & 15)) * 80 +
                                               ((lane >> 4) * 16) + s * 32);
                ldsm4(aH[i], ab);
                ldsm4(aL[i], ab + APL);
            }
            int krow = s * 16 + (lane & 15);
            uint32_t ksw = (uint32_t)((krow & 7) * 16);
            uint32_t rowb = (uint32_t)(krow * 256);
            uint32_t bf[4][2];
#pragma unroll
            for (int j2 = 0; j2 < 2; j2++) {
                uint32_t chunk = (((uint32_t)((wn + j2 * 16) * 2 + (lane >> 4) * 16)) ^ ksw);
                uint32_t r[4];
                ldsm4t(r, stb + BOFF + rowb + chunk);
                bf[j2 * 2][0] = r[0]; bf[j2 * 2][1] = r[1];
                bf[j2 * 2 + 1][0] = r[2]; bf[j2 * 2 + 1][1] = r[3];
            }
#pragma unroll
            for (int i = 0; i < 4; i++)
#pragma unroll
                for (int j = 0; j < 4; j++)
                    mma16816(acc[i][j], aH[i], bf[j]);
#pragma unroll
            for (int i = 0; i < 4; i++)
#pragma unroll
                for (int j = 0; j < 4; j++)
                    mma16816(acc[i][j], aL[i], bf[j]);
            // lo B plane
#pragma unroll
            for (int j2 = 0; j2 < 2; j2++) {
                uint32_t chunk = (((uint32_t)((wn + j2 * 16) * 2 + (lane >> 4) * 16)) ^ ksw);
                uint32_t r[4];
                ldsm4t(r, stb + BOFF + 8192 + rowb + chunk);
                bf[j2 * 2][0] = r[0]; bf[j2 * 2][1] = r[1];
                bf[j2 * 2 + 1][0] = r[2]; bf[j2 * 2 + 1][1] = r[3];
            }
#pragma unroll
            for (int i = 0; i < 4; i++)
#pragma unroll
                for (int j = 0; j < 4; j++)
                    mma16816(acc[i][j], aH[i], bf[j]);
        }
        if (c < 63) G2_STS(SB + (uint32_t)((c + 1) & 1) * STAGE);
        __syncthreads();
    }

    // epilogue: weighted atomic scatter-add (2 adds/elem total -> deterministic)
    int r0 = lane >> 2, cc = 2 * (lane & 3);
#pragma unroll
    for (int i = 0; i < 4; i++)
#pragma unroll
        for (int h = 0; h < 2; h++) {
            int row = row_start + wm + i * 16 + r0 + h * 8;
            int tok = g_row_token[row];
            if (tok < 0) continue;
            float w = g_row_weight[row];
            float* ob = out + (size_t)tok * HDIM + n0;
#pragma unroll
            for (int j = 0; j < 4; j++) {
                int col = wn + j * 8 + cc;
                atomicAdd(ob + col,     w * acc[i][j][2 * h]);
                atomicAdd(ob + col + 1, w * acc[i][j][2 * h + 1]);
            }
        }
#undef G2_LDG
#undef G2_STS
}

// ---------------- launch -----------------------------------------------------
extern "C" void kernel_launch(void* const* d_in, const int* in_sizes, int n_in,
                              void* d_out, int out_size) {
    const float* x  = (const float*)d_in[0];
    const float* gw = (const float*)d_in[1];
    const float* w1 = (const float*)d_in[2];
    const float* w3 = (const float*)d_in[3];
    const float* w2 = (const float*)d_in[4];
    float* out = (float*)d_out;

    static int attr_done = 0;
    if (!attr_done) {
        cudaFuncSetAttribute(gemm1_kernel, cudaFuncAttributeMaxDynamicSharedMemorySize, 2 * STAGE);
        cudaFuncSetAttribute(gemm2_kernel, cudaFuncAttributeMaxDynamicSharedMemorySize, 2 * STAGE);
        attr_done = 1;
    }

    reset_kernel<<<(T_TOK * HDIM + 255) / 256, 256>>>(out);
    router_kernel<<<T_TOK, 256>>>(x, gw);
    plan_kernel<<<1, 32>>>();
    scatter_kernel<<<(T_TOK + 255) / 256, 256>>>();

    gemm1_kernel<<<dim3(32, MAX_TILES), 256, 2 * STAGE>>>(x, w1, w3);
    gemm2_kernel<<<dim3(16, MAX_TILES), 256, 2 * STAGE>>>(w2, out);
}

// round 6
// speedup vs baseline: 2.3787x; 1.1392x over previous
#include <cuda_runtime.h>
#include <cuda_fp16.h>
#include <cstdint>

#define T_TOK 2048
#define HDIM  2048
#define IDIM  2048
#define NEXP  8
#define ROWS_PAD 5120          // 40 tiles * 128
#define MAX_TILES 40
#define WMAT ((size_t)2048 * 2048)

// stage layout (bytes, both GEMMs): Ah 0..10239, Al 10240..20479, B hi planes at 20480+
#define APL   10240            // 128 rows * 80B (32 fp16 + 8 pad)
#define BOFF  20480
#define STAGE 28672            // 20480 + 8192 (B hi only)

// ---------------- device scratch ---------------------------------------------
__device__ uint32_t g_act[(size_t)ROWS_PAD * IDIM]; // silu(g)*u packed (hi<<16|lo) fp16
__device__ int   g_row_token[ROWS_PAD];
__device__ float g_row_weight[ROWS_PAD];
__device__ int   g_tok_e[2 * T_TOK];
__device__ float g_tok_w[2 * T_TOK];
__device__ int   g_counts[NEXP];
__device__ int   g_cursor[NEXP];
__device__ int   g_seg_start[NEXP];
__device__ int   g_tile_e[MAX_TILES];
__device__ int   g_tile_row[MAX_TILES];

// ---------------- helpers ----------------------------------------------------
__device__ __forceinline__ uint32_t smem_u32(const void* p) {
    return (uint32_t)__cvta_generic_to_shared(p);
}
__device__ __forceinline__ void mma16816(float* c, const uint32_t* a, const uint32_t* b) {
    asm volatile(
        "mma.sync.aligned.m16n8k16.row.col.f32.f16.f16.f32 "
        "{%0,%1,%2,%3}, {%4,%5,%6,%7}, {%8,%9}, {%0,%1,%2,%3};"
        : "+f"(c[0]), "+f"(c[1]), "+f"(c[2]), "+f"(c[3])
        : "r"(a[0]), "r"(a[1]), "r"(a[2]), "r"(a[3]), "r"(b[0]), "r"(b[1]));
}
__device__ __forceinline__ void ldsm4(uint32_t* r, uint32_t a) {
    asm volatile("ldmatrix.sync.aligned.m8n8.x4.shared.b16 {%0,%1,%2,%3}, [%4];"
        : "=r"(r[0]), "=r"(r[1]), "=r"(r[2]), "=r"(r[3]) : "r"(a));
}
__device__ __forceinline__ void ldsm4t(uint32_t* r, uint32_t a) {
    asm volatile("ldmatrix.sync.aligned.m8n8.x4.trans.shared.b16 {%0,%1,%2,%3}, [%4];"
        : "=r"(r[0]), "=r"(r[1]), "=r"(r[2]), "=r"(r[3]) : "r"(a));
}
__device__ __forceinline__ void sts4(uint32_t a, uint32_t v0, uint32_t v1, uint32_t v2, uint32_t v3) {
    asm volatile("st.shared.v4.b32 [%0], {%1,%2,%3,%4};" :: "r"(a), "r"(v0), "r"(v1), "r"(v2), "r"(v3) : "memory");
}
__device__ __forceinline__ uint32_t prmt32(uint32_t a, uint32_t b, uint32_t s) {
    uint32_t r; asm("prmt.b32 %0,%1,%2,%3;" : "=r"(r) : "r"(a), "r"(b), "r"(s)); return r;
}
// fp16 split: x = hi + lo (hi = rn(x), lo = rn(x - hi)); packs pairs into b32 lanes
__device__ __forceinline__ void split2(float a, float b, uint32_t& hi, uint32_t& lo) {
    __half2 h = __floats2half2_rn(a, b);   // .x -> low 16 bits
    float2 hf = __half22float2(h);
    __half2 l = __floats2half2_rn(a - hf.x, b - hf.y);
    hi = *(uint32_t*)&h;
    lo = *(uint32_t*)&l;
}
__device__ __forceinline__ uint32_t cvt2(float a, float b) {
    __half2 h = __floats2half2_rn(a, b);
    return *(uint32_t*)&h;
}
__device__ __forceinline__ uint32_t packhl(float v) {
    __half h = __float2half_rn(v);
    float r = v - __half2float(h);
    __half l = __float2half_rn(r);
    return ((uint32_t)__half_as_ushort(h) << 16) | (uint32_t)__half_as_ushort(l);
}

// ---------------- reset ------------------------------------------------------
__global__ void reset_kernel(float* __restrict__ out) {
    int idx = blockIdx.x * 256 + threadIdx.x;
    if (idx < T_TOK * HDIM) out[idx] = 0.0f;
    if (idx < ROWS_PAD) g_row_token[idx] = -1;
    if (idx < NEXP) { g_counts[idx] = 0; g_cursor[idx] = 0; }
}

// ---------------- router -----------------------------------------------------
__global__ __launch_bounds__(256) void router_kernel(const float* __restrict__ x,
                                                     const float* __restrict__ gw) {
    int t = blockIdx.x;
    const float* xr = x + (size_t)t * HDIM;
    float acc[NEXP];
#pragma unroll
    for (int e = 0; e < NEXP; e++) acc[e] = 0.0f;
    for (int h = threadIdx.x; h < HDIM; h += 256) {
        float xv = xr[h];
#pragma unroll
        for (int e = 0; e < NEXP; e++) acc[e] = fmaf(xv, gw[e * HDIM + h], acc[e]);
    }
#pragma unroll
    for (int off = 16; off > 0; off >>= 1)
#pragma unroll
        for (int e = 0; e < NEXP; e++)
            acc[e] += __shfl_down_sync(0xffffffffu, acc[e], off);

    __shared__ float red[8][NEXP];
    int wid = threadIdx.x >> 5, lane = threadIdx.x & 31;
    if (lane == 0)
#pragma unroll
        for (int e = 0; e < NEXP; e++) red[wid][e] = acc[e];
    __syncthreads();

    if (threadIdx.x == 0) {
        float l[NEXP];
#pragma unroll
        for (int e = 0; e < NEXP; e++) {
            float s = 0.0f;
#pragma unroll
            for (int w = 0; w < 8; w++) s += red[w][e];
            l[e] = s;
        }
        int i0 = 0;
#pragma unroll
        for (int e = 1; e < NEXP; e++) if (l[e] > l[i0]) i0 = e;
        int i1 = -1;
#pragma unroll
        for (int e = 0; e < NEXP; e++)
            if (e != i0 && (i1 < 0 || l[e] > l[i1])) i1 = e;
        float w0 = 1.0f / (1.0f + expf(l[i1] - l[i0]));
        float w1 = 1.0f - w0;
        g_tok_e[2 * t] = i0;     g_tok_e[2 * t + 1] = i1;
        g_tok_w[2 * t] = w0;     g_tok_w[2 * t + 1] = w1;
        atomicAdd(&g_counts[i0], 1);
        atomicAdd(&g_counts[i1], 1);
    }
}

// ---------------- plan + scatter ---------------------------------------------
__global__ void plan_kernel() {
    if (threadIdx.x != 0) return;
    int off = 0, tile = 0;
    for (int e = 0; e < NEXP; e++) {
        g_seg_start[e] = off;
        int n = g_counts[e];
        int nt = (n + 127) >> 7;
        for (int j = 0; j < nt; j++) { g_tile_e[tile] = e; g_tile_row[tile] = off + (j << 7); tile++; }
        off += nt << 7;
    }
    for (; tile < MAX_TILES; tile++) g_tile_e[tile] = -1;
}

__global__ void scatter_kernel() {
    int t = blockIdx.x * 256 + threadIdx.x;
    if (t >= T_TOK) return;
#pragma unroll
    for (int k = 0; k < 2; k++) {
        int e = g_tok_e[2 * t + k];
        int r = atomicAdd(&g_cursor[e], 1);
        int row = g_seg_start[e] + r;
        g_row_token[row] = t;
        g_row_weight[row] = g_tok_w[2 * t + k];
    }
}

// ---------------- GEMM1: HMMA fp16 split-2, fused gate+up + SiLU -------------
// CTA: M=128, N=64 (per mat), KC=32. 8 warps = 4(M) x 2(N), warp 32x32, dual acc.
__global__ __launch_bounds__(256) void gemm1_kernel(const float* __restrict__ x,
                                                    const float* __restrict__ w1,
                                                    const float* __restrict__ w3) {
    int e = g_tile_e[blockIdx.y];
    if (e < 0) return;
    int row_start = g_tile_row[blockIdx.y];
    int n0 = blockIdx.x * 64;
    extern __shared__ __align__(1024) char smem[];
    uint32_t SB = smem_u32(smem);

    const int tid = threadIdx.x;
    const int lane = tid & 31, wid = tid >> 5;
    const int wm = (wid & 3) * 32, wn = (wid >> 2) * 32;

    // staging maps
    const int bmat = tid >> 7;                  // 0:w1  1:w3
    const int bk = (tid & 127) >> 2;            // 0..31
    const int bn = (tid & 3) * 16;              // float col offset
    const float* bsrc = (bmat ? w3 : w1) + (size_t)e * WMAT + (size_t)bk * IDIM + n0 + bn;
    const int ar = tid >> 1;                    // 0..127
    const int akh = (tid & 1) * 16;
    int tok0 = g_row_token[row_start + ar];
    const float* asrc = (tok0 >= 0) ? x + (size_t)tok0 * HDIM + akh : (const float*)0;

    const uint32_t a_sts = (uint32_t)(ar * 80 + akh * 2);
    const uint32_t bswz = (uint32_t)((bk & 7) * 16);
    const uint32_t b_base = (uint32_t)(BOFF + bmat * 4096 + bk * 128);
    const uint32_t b_sts0 = b_base + (((uint32_t)(bn * 2)) ^ bswz);
    const uint32_t b_sts1 = b_base + (((uint32_t)(bn * 2 + 16)) ^ bswz);

    float4 ra[4], rb[4];
    float accG[2][4][4], accU[2][4][4];
#pragma unroll
    for (int i = 0; i < 2; i++)
#pragma unroll
        for (int j = 0; j < 4; j++)
#pragma unroll
            for (int q = 0; q < 4; q++) { accG[i][j][q] = 0.0f; accU[i][j][q] = 0.0f; }

#define G1_LDG(c) do { int k0 = (c) * 32;                                         \
        if (asrc) { ra[0] = *(const float4*)(asrc + k0);                          \
                    ra[1] = *(const float4*)(asrc + k0 + 4);                      \
                    ra[2] = *(const float4*)(asrc + k0 + 8);                      \
                    ra[3] = *(const float4*)(asrc + k0 + 12); }                   \
        else { ra[0] = make_float4(0.f,0.f,0.f,0.f); ra[1]=ra[0]; ra[2]=ra[0]; ra[3]=ra[0]; } \
        const float* bp = bsrc + (size_t)k0 * IDIM;                               \
        rb[0] = *(const float4*)(bp);      rb[1] = *(const float4*)(bp + 4);      \
        rb[2] = *(const float4*)(bp + 8);  rb[3] = *(const float4*)(bp + 12);     \
    } while (0)

#define G1_STS(stb) do {                                                          \
        uint32_t h[8], l[8];                                                      \
        split2(ra[0].x, ra[0].y, h[0], l[0]); split2(ra[0].z, ra[0].w, h[1], l[1]); \
        split2(ra[1].x, ra[1].y, h[2], l[2]); split2(ra[1].z, ra[1].w, h[3], l[3]); \
        split2(ra[2].x, ra[2].y, h[4], l[4]); split2(ra[2].z, ra[2].w, h[5], l[5]); \
        split2(ra[3].x, ra[3].y, h[6], l[6]); split2(ra[3].z, ra[3].w, h[7], l[7]); \
        sts4((stb) + a_sts,        h[0], h[1], h[2], h[3]);                       \
        sts4((stb) + a_sts + 16,   h[4], h[5], h[6], h[7]);                       \
        sts4((stb) + APL + a_sts,      l[0], l[1], l[2], l[3]);                   \
        sts4((stb) + APL + a_sts + 16, l[4], l[5], l[6], l[7]);                   \
        h[0] = cvt2(rb[0].x, rb[0].y); h[1] = cvt2(rb[0].z, rb[0].w);             \
        h[2] = cvt2(rb[1].x, rb[1].y); h[3] = cvt2(rb[1].z, rb[1].w);             \
        h[4] = cvt2(rb[2].x, rb[2].y); h[5] = cvt2(rb[2].z, rb[2].w);             \
        h[6] = cvt2(rb[3].x, rb[3].y); h[7] = cvt2(rb[3].z, rb[3].w);             \
        sts4((stb) + b_sts0, h[0], h[1], h[2], h[3]);                             \
        sts4((stb) + b_sts1, h[4], h[5], h[6], h[7]);                             \
    } while (0)

    G1_LDG(0);
    G1_STS(SB);
    __syncthreads();

    for (int c = 0; c < 64; c++) {
        uint32_t stb = SB + (uint32_t)(c & 1) * STAGE;
        if (c < 63) G1_LDG(c + 1);
#pragma unroll
        for (int s = 0; s < 2; s++) {
            uint32_t aH[2][4], aL[2][4];
#pragma unroll
            for (int i = 0; i < 2; i++) {
                uint32_t ab = stb + (uint32_t)((wm + i * 16 + (lane & 15)) * 80 +
                                               ((lane >> 4) * 16) + s * 32);
                ldsm4(aH[i], ab);
                ldsm4(aL[i], ab + APL);
            }
            int krow = s * 16 + (lane & 15);
            uint32_t ksw = (uint32_t)((krow & 7) * 16);
            uint32_t rowb = (uint32_t)(krow * 128);
            uint32_t bf[2][4][2];
#pragma unroll
            for (int m = 0; m < 2; m++)
#pragma unroll
                for (int j2 = 0; j2 < 2; j2++) {
                    uint32_t chunk = (((uint32_t)((wn + j2 * 16) * 2 + (lane >> 4) * 16)) ^ ksw);
                    uint32_t r[4];
                    ldsm4t(r, stb + BOFF + (uint32_t)m * 4096 + rowb + chunk);
                    bf[m][j2 * 2][0] = r[0]; bf[m][j2 * 2][1] = r[1];
                    bf[m][j2 * 2 + 1][0] = r[2]; bf[m][j2 * 2 + 1][1] = r[3];
                }
            // products Ah*B, Al*B
#pragma unroll
            for (int i = 0; i < 2; i++)
#pragma unroll
                for (int j = 0; j < 4; j++) {
                    mma16816(accG[i][j], aH[i], bf[0][j]);
                    mma16816(accU[i][j], aH[i], bf[1][j]);
                }
#pragma unroll
            for (int i = 0; i < 2; i++)
#pragma unroll
                for (int j = 0; j < 4; j++) {
                    mma16816(accG[i][j], aL[i], bf[0][j]);
                    mma16816(accU[i][j], aL[i], bf[1][j]);
                }
        }
        if (c < 63) G1_STS(SB + (uint32_t)((c + 1) & 1) * STAGE);
        __syncthreads();
    }

    // epilogue: silu(G)*U packed hi/lo -> g_act
    int r0 = lane >> 2, cc = 2 * (lane & 3);
#pragma unroll
    for (int i = 0; i < 2; i++)
#pragma unroll
        for (int j = 0; j < 4; j++) {
            int col = n0 + wn + j * 8 + cc;
#pragma unroll
            for (int h = 0; h < 2; h++) {
                int row = row_start + wm + i * 16 + r0 + h * 8;
                float g0 = accG[i][j][2 * h],     u0 = accU[i][j][2 * h];
                float g1 = accG[i][j][2 * h + 1], u1 = accU[i][j][2 * h + 1];
                float a0 = (g0 / (1.0f + __expf(-g0))) * u0;
                float a1 = (g1 / (1.0f + __expf(-g1))) * u1;
                *(uint2*)&g_act[(size_t)row * IDIM + col] = make_uint2(packhl(a0), packhl(a1));
            }
        }
#undef G1_LDG
#undef G1_STS
}

// ---------------- GEMM2: HMMA fp16 split-2, down proj + weighted scatter-add -
// CTA: M=128, N=128, KC=32. 8 warps = 2(M) x 4(N), warp 64x32.
__global__ __launch_bounds__(256) void gemm2_kernel(const float* __restrict__ w2,
                                                    float* __restrict__ out) {
    int e = g_tile_e[blockIdx.y];
    if (e < 0) return;
    int row_start = g_tile_row[blockIdx.y];
    int n0 = blockIdx.x * 128;
    extern __shared__ __align__(1024) char smem[];
    uint32_t SB = smem_u32(smem);

    const int tid = threadIdx.x;
    const int lane = tid & 31, wid = tid >> 5;
    const int wm = (wid & 1) * 64, wn = (wid >> 1) * 32;

    const int ar = tid >> 1;
    const int akh = (tid & 1) * 16;
    const uint32_t* asrc = g_act + (size_t)(row_start + ar) * IDIM + akh;
    const int bk = tid >> 3;                    // 0..31
    const int bn = (tid & 7) * 16;
    const float* bsrc = w2 + (size_t)e * WMAT + (size_t)bk * HDIM + n0 + bn;

    const uint32_t a_sts = (uint32_t)(ar * 80 + akh * 2);
    const uint32_t bswz = (uint32_t)((bk & 7) * 16);
    const uint32_t b_base = (uint32_t)(BOFF + bk * 256);
    const uint32_t b_sts0 = b_base + (((uint32_t)(bn * 2)) ^ bswz);
    const uint32_t b_sts1 = b_base + (((uint32_t)(bn * 2 + 16)) ^ bswz);

    uint4 pa[4];
    float4 rb[4];
    float acc[4][4][4];
#pragma unroll
    for (int i = 0; i < 4; i++)
#pragma unroll
        for (int j = 0; j < 4; j++)
#pragma unroll
            for (int q = 0; q < 4; q++) acc[i][j][q] = 0.0f;

#define G2_LDG(c) do { int k0 = (c) * 32;                                         \
        pa[0] = *(const uint4*)(asrc + k0);     pa[1] = *(const uint4*)(asrc + k0 + 4); \
        pa[2] = *(const uint4*)(asrc + k0 + 8); pa[3] = *(const uint4*)(asrc + k0 + 12); \
        const float* bp = bsrc + (size_t)k0 * HDIM;                               \
        rb[0] = *(const float4*)(bp);      rb[1] = *(const float4*)(bp + 4);      \
        rb[2] = *(const float4*)(bp + 8);  rb[3] = *(const float4*)(bp + 12);     \
    } while (0)

#define G2_STS(stb) do {                                                          \
        uint32_t h[8], l[8];                                                      \
        h[0] = prmt32(pa[0].x, pa[0].y, 0x7632u); l[0] = prmt32(pa[0].x, pa[0].y, 0x5410u); \
        h[1] = prmt32(pa[0].z, pa[0].w, 0x7632u); l[1] = prmt32(pa[0].z, pa[0].w, 0x5410u); \
        h[2] = prmt32(pa[1].x, pa[1].y, 0x7632u); l[2] = prmt32(pa[1].x, pa[1].y, 0x5410u); \
        h[3] = prmt32(pa[1].z, pa[1].w, 0x7632u); l[3] = prmt32(pa[1].z, pa[1].w, 0x5410u); \
        h[4] = prmt32(pa[2].x, pa[2].y, 0x7632u); l[4] = prmt32(pa[2].x, pa[2].y, 0x5410u); \
        h[5] = prmt32(pa[2].z, pa[2].w, 0x7632u); l[5] = prmt32(pa[2].z, pa[2].w, 0x5410u); \
        h[6] = prmt32(pa[3].x, pa[3].y, 0x7632u); l[6] = prmt32(pa[3].x, pa[3].y, 0x5410u); \
        h[7] = prmt32(pa[3].z, pa[3].w, 0x7632u); l[7] = prmt32(pa[3].z, pa[3].w, 0x5410u); \
        sts4((stb) + a_sts,        h[0], h[1], h[2], h[3]);                       \
        sts4((stb) + a_sts + 16,   h[4], h[5], h[6], h[7]);                       \
        sts4((stb) + APL + a_sts,      l[0], l[1], l[2], l[3]);                   \
        sts4((stb) + APL + a_sts + 16, l[4], l[5], l[6], l[7]);                   \
        h[0] = cvt2(rb[0].x, rb[0].y); h[1] = cvt2(rb[0].z, rb[0].w);             \
        h[2] = cvt2(rb[1].x, rb[1].y); h[3] = cvt2(rb[1].z, rb[1].w);             \
        h[4] = cvt2(rb[2].x, rb[2].y); h[5] = cvt2(rb[2].z, rb[2].w);             \
        h[6] = cvt2(rb[3].x, rb[3].y); h[7] = cvt2(rb[3].z, rb[3].w);             \
        sts4((stb) + b_sts0, h[0], h[1], h[2], h[3]);                             \
        sts4((stb) + b_sts1, h[4], h[5], h[6], h[7]);                             \
    } while (0)

    G2_LDG(0);
    G2_STS(SB);
    __syncthreads();

    for (int c = 0; c < 64; c++) {
        uint32_t stb = SB + (uint32_t)(c & 1) * STAGE;
        if (c < 63) G2_LDG(c + 1);
#pragma unroll
        for (int s = 0; s < 2; s++) {
            uint32_t aH[4][4], aL[4][4];
#pragma unroll
            for (int i = 0; i < 4; i++) {
                uint32_t ab = stb + (uint32_t)((wm + i * 16 + (lane & 15)) * 80 +
                                               ((lane >> 4) * 16) + s * 32);
                ldsm4(aH[i], ab);
                ldsm4(aL[i], ab + APL);
            }
            int krow = s * 16 + (lane & 15);
            uint32_t ksw = (uint32_t)((krow & 7) * 16);
            uint32_t rowb = (uint32_t)(krow * 256);
            uint32_t bf[4][2];
#pragma unroll
            for (int j2 = 0; j2 < 2; j2++) {
                uint32_t chunk = (((uint32_t)((wn + j2 * 16) * 2 + (lane >> 4) * 16)) ^ ksw);
                uint32_t r[4];
                ldsm4t(r, stb + BOFF + rowb + chunk);
                bf[j2 * 2][0] = r[0]; bf[j2 * 2][1] = r[1];
                bf[j2 * 2 + 1][0] = r[2]; bf[j2 * 2 + 1][1] = r[3];
            }
#pragma unroll
            for (int i = 0; i < 4; i++)
#pragma unroll
                for (int j = 0; j < 4; j++)
                    mma16816(acc[i][j], aH[i], bf[j]);
#pragma unroll
            for (int i = 0; i < 4; i++)
#pragma unroll
                for (int j = 0; j < 4; j++)
                    mma16816(acc[i][j], aL[i], bf[j]);
        }
        if (c < 63) G2_STS(SB + (uint32_t)((c + 1) & 1) * STAGE);
        __syncthreads();
    }

    // epilogue: weighted atomic scatter-add (2 adds/elem total -> deterministic)
    int r0 = lane >> 2, cc = 2 * (lane & 3);
#pragma unroll
    for (int i = 0; i < 4; i++)
#pragma unroll
        for (int h = 0; h < 2; h++) {
            int row = row_start + wm + i * 16 + r0 + h * 8;
            int tok = g_row_token[row];
            if (tok < 0) continue;
            float w = g_row_weight[row];
            float* ob = out + (size_t)tok * HDIM + n0;
#pragma unroll
            for (int j = 0; j < 4; j++) {
                int col = wn + j * 8 + cc;
                atomicAdd(ob + col,     w * acc[i][j][2 * h]);
                atomicAdd(ob + col + 1, w * acc[i][j][2 * h + 1]);
            }
        }
#undef G2_LDG
#undef G2_STS
}

// ---------------- launch -----------------------------------------------------
extern "C" void kernel_launch(void* const* d_in, const int* in_sizes, int n_in,
                              void* d_out, int out_size) {
    const float* x  = (const float*)d_in[0];
    const float* gw = (const float*)d_in[1];
    const float* w1 = (const float*)d_in[2];
    const float* w3 = (const float*)d_in[3];
    const float* w2 = (const float*)d_in[4];
    float* out = (float*)d_out;

    static int attr_done = 0;
    if (!attr_done) {
        cudaFuncSetAttribute(gemm1_kernel, cudaFuncAttributeMaxDynamicSharedMemorySize, 2 * STAGE);
        cudaFuncSetAttribute(gemm2_kernel, cudaFuncAttributeMaxDynamicSharedMemorySize, 2 * STAGE);
        attr_done = 1;
    }

    reset_kernel<<<(T_TOK * HDIM + 255) / 256, 256>>>(out);
    router_kernel<<<T_TOK, 256>>>(x, gw);
    plan_kernel<<<1, 32>>>();
    scatter_kernel<<<(T_TOK + 255) / 256, 256>>>();

    gemm1_kernel<<<dim3(32, MAX_TILES), 256, 2 * STAGE>>>(x, w1, w3);
    gemm2_kernel<<<dim3(16, MAX_TILES), 256, 2 * STAGE>>>(w2, out);
}

// round 7
// speedup vs baseline: 3.0448x; 1.2800x over previous
#include <cuda_runtime.h>
#include <cuda_fp16.h>
#include <cstdint>

#define T_TOK 2048
#define HDIM  2048
#define IDIM  2048
#define NEXP  8
#define ROWS_PAD 5120          // 40 tiles * 128
#define MAX_TILES 40
#define WMAT ((size_t)2048 * 2048)

// gemm1 stage: Ah 0..10239, Al 10240..20479, B(2 mats fp16) 20480..28671
#define APL    10240           // 128 rows * 80B (32 fp16 + 8B pad)
#define BOFF1  20480
#define STAGE1 28672
// gemm2 stage: A 0..10239, B 10240..18431
#define BOFF2  10240
#define STAGE2 18432

// ---------------- device scratch ---------------------------------------------
__device__ __half   g_w1h[NEXP * WMAT];   // fp16 weights, same [E][K][N] layout
__device__ __half   g_w3h[NEXP * WMAT];
__device__ __half   g_w2h[NEXP * WMAT];
__device__ uint32_t g_xhl[(size_t)T_TOK * HDIM];    // x packed (hi<<16 | lo) fp16
__device__ __half   g_acth[(size_t)ROWS_PAD * IDIM]; // silu(g)*u fp16
__device__ int   g_row_token[ROWS_PAD];
__device__ float g_row_weight[ROWS_PAD];
__device__ int   g_tok_e[2 * T_TOK];
__device__ float g_tok_w[2 * T_TOK];
__device__ int   g_counts[NEXP];
__device__ int   g_cursor[NEXP];
__device__ int   g_seg_start[NEXP];
__device__ int   g_tile_e[MAX_TILES];
__device__ int   g_tile_row[MAX_TILES];

// ---------------- helpers ----------------------------------------------------
__device__ __forceinline__ uint32_t smem_u32(const void* p) {
    return (uint32_t)__cvta_generic_to_shared(p);
}
__device__ __forceinline__ void mma16816(float* c, const uint32_t* a, const uint32_t* b) {
    asm volatile(
        "mma.sync.aligned.m16n8k16.row.col.f32.f16.f16.f32 "
        "{%0,%1,%2,%3}, {%4,%5,%6,%7}, {%8,%9}, {%0,%1,%2,%3};"
        : "+f"(c[0]), "+f"(c[1]), "+f"(c[2]), "+f"(c[3])
        : "r"(a[0]), "r"(a[1]), "r"(a[2]), "r"(a[3]), "r"(b[0]), "r"(b[1]));
}
__device__ __forceinline__ void ldsm4(uint32_t* r, uint32_t a) {
    asm volatile("ldmatrix.sync.aligned.m8n8.x4.shared.b16 {%0,%1,%2,%3}, [%4];"
        : "=r"(r[0]), "=r"(r[1]), "=r"(r[2]), "=r"(r[3]) : "r"(a));
}
__device__ __forceinline__ void ldsm4t(uint32_t* r, uint32_t a) {
    asm volatile("ldmatrix.sync.aligned.m8n8.x4.trans.shared.b16 {%0,%1,%2,%3}, [%4];"
        : "=r"(r[0]), "=r"(r[1]), "=r"(r[2]), "=r"(r[3]) : "r"(a));
}
__device__ __forceinline__ void sts4(uint32_t a, uint32_t v0, uint32_t v1, uint32_t v2, uint32_t v3) {
    asm volatile("st.shared.v4.b32 [%0], {%1,%2,%3,%4};" :: "r"(a), "r"(v0), "r"(v1), "r"(v2), "r"(v3) : "memory");
}
__device__ __forceinline__ uint32_t prmt32(uint32_t a, uint32_t b, uint32_t s) {
    uint32_t r; asm("prmt.b32 %0,%1,%2,%3;" : "=r"(r) : "r"(a), "r"(b), "r"(s)); return r;
}
__device__ __forceinline__ uint32_t cvt2(float a, float b) {
    __half2 h = __floats2half2_rn(a, b);
    return *(uint32_t*)&h;
}
__device__ __forceinline__ uint32_t packhl(float v) {
    __half h = __float2half_rn(v);
    float r = v - __half2float(h);
    __half l = __float2half_rn(r);
    return ((uint32_t)__half_as_ushort(h) << 16) | (uint32_t)__half_as_ushort(l);
}

// ---------------- reset ------------------------------------------------------
__global__ void reset_kernel(float* __restrict__ out) {
    int idx = blockIdx.x * 256 + threadIdx.x;
    if (idx < T_TOK * HDIM) out[idx] = 0.0f;
    if (idx < ROWS_PAD) g_row_token[idx] = -1;
    if (idx < NEXP) { g_counts[idx] = 0; g_cursor[idx] = 0; }
}

// ---------------- router -----------------------------------------------------
__global__ __launch_bounds__(256) void router_kernel(const float* __restrict__ x,
                                                     const float* __restrict__ gw) {
    int t = blockIdx.x;
    const float* xr = x + (size_t)t * HDIM;
    float acc[NEXP];
#pragma unroll
    for (int e = 0; e < NEXP; e++) acc[e] = 0.0f;
    for (int h = threadIdx.x; h < HDIM; h += 256) {
        float xv = xr[h];
#pragma unroll
        for (int e = 0; e < NEXP; e++) acc[e] = fmaf(xv, gw[e * HDIM + h], acc[e]);
    }
#pragma unroll
    for (int off = 16; off > 0; off >>= 1)
#pragma unroll
        for (int e = 0; e < NEXP; e++)
            acc[e] += __shfl_down_sync(0xffffffffu, acc[e], off);

    __shared__ float red[8][NEXP];
    int wid = threadIdx.x >> 5, lane = threadIdx.x & 31;
    if (lane == 0)
#pragma unroll
        for (int e = 0; e < NEXP; e++) red[wid][e] = acc[e];
    __syncthreads();

    if (threadIdx.x == 0) {
        float l[NEXP];
#pragma unroll
        for (int e = 0; e < NEXP; e++) {
            float s = 0.0f;
#pragma unroll
            for (int w = 0; w < 8; w++) s += red[w][e];
            l[e] = s;
        }
        int i0 = 0;
#pragma unroll
        for (int e = 1; e < NEXP; e++) if (l[e] > l[i0]) i0 = e;
        int i1 = -1;
#pragma unroll
        for (int e = 0; e < NEXP; e++)
            if (e != i0 && (i1 < 0 || l[e] > l[i1])) i1 = e;
        float w0 = 1.0f / (1.0f + expf(l[i1] - l[i0]));
        float w1 = 1.0f - w0;
        g_tok_e[2 * t] = i0;     g_tok_e[2 * t + 1] = i1;
        g_tok_w[2 * t] = w0;     g_tok_w[2 * t + 1] = w1;
        atomicAdd(&g_counts[i0], 1);
        atomicAdd(&g_counts[i1], 1);
    }
}

// ---------------- plan + scatter ---------------------------------------------
__global__ void plan_kernel() {
    if (threadIdx.x != 0) return;
    int off = 0, tile = 0;
    for (int e = 0; e < NEXP; e++) {
        g_seg_start[e] = off;
        int n = g_counts[e];
        int nt = (n + 127) >> 7;
        for (int j = 0; j < nt; j++) { g_tile_e[tile] = e; g_tile_row[tile] = off + (j << 7); tile++; }
        off += nt << 7;
    }
    for (; tile < MAX_TILES; tile++) g_tile_e[tile] = -1;
}

__global__ void scatter_kernel() {
    int t = blockIdx.x * 256 + threadIdx.x;
    if (t >= T_TOK) return;
#pragma unroll
    for (int k = 0; k < 2; k++) {
        int e = g_tok_e[2 * t + k];
        int r = atomicAdd(&g_cursor[e], 1);
        int row = g_seg_start[e] + r;
        g_row_token[row] = t;
        g_row_weight[row] = g_tok_w[2 * t + k];
    }
}

// ---------------- prep: weights fp32 -> fp16, x fp32 -> packed hi/lo ---------
__global__ __launch_bounds__(256) void prep_w_kernel(const float* __restrict__ w1,
                                                     const float* __restrict__ w3,
                                                     const float* __restrict__ w2) {
    int mat = blockIdx.y;
    const float* src = (mat == 0 ? w1 : (mat == 1 ? w3 : w2));
    __half* dst = (mat == 0 ? g_w1h : (mat == 1 ? g_w3h : g_w2h));
    size_t i = ((size_t)blockIdx.x * 256 + threadIdx.x);
    // 8 experts * 4M elems / 4 per thread = 8.388.608 float4 per matrix
    float4 v = *(const float4*)(src + 4 * i);
    uint2 o;
    o.x = cvt2(v.x, v.y);
    o.y = cvt2(v.z, v.w);
    *(uint2*)(dst + 4 * i) = o;
}

__global__ __launch_bounds__(256) void prep_x_kernel(const float* __restrict__ x) {
    size_t i = ((size_t)blockIdx.x * 256 + threadIdx.x);
    float4 v = *(const float4*)(x + 4 * i);
    uint4 o;
    o.x = packhl(v.x); o.y = packhl(v.y); o.z = packhl(v.z); o.w = packhl(v.w);
    *(uint4*)(g_xhl + 4 * i) = o;
}

// ---------------- GEMM1: HMMA fp16 A-split-2, fused gate+up + SiLU -----------
// CTA: M=128, N=64 (per mat), KC=32. 8 warps = 4(M) x 2(N), warp 32x32, dual acc.
__global__ __launch_bounds__(256) void gemm1_kernel() {
    int e = g_tile_e[blockIdx.y];
    if (e < 0) return;
    int row_start = g_tile_row[blockIdx.y];
    int n0 = blockIdx.x * 64;
    extern __shared__ __align__(1024) char smem[];
    uint32_t SB = smem_u32(smem);

    const int tid = threadIdx.x;
    const int lane = tid & 31, wid = tid >> 5;
    const int wm = (wid & 3) * 32, wn = (wid >> 2) * 32;

    // staging maps
    const int bmat = tid >> 7;                  // 0:w1  1:w3
    const int bk = (tid & 127) >> 2;            // 0..31
    const int bn = (tid & 3) * 16;              // half col offset
    const __half* bsrc = (bmat ? g_w3h : g_w1h) + (size_t)e * WMAT + (size_t)bk * IDIM + n0 + bn;
    const int ar = tid >> 1;                    // 0..127
    const int akh = (tid & 1) * 16;             // K elems
    int tok0 = g_row_token[row_start + ar];
    const uint32_t* asrc = (tok0 >= 0) ? g_xhl + (size_t)tok0 * HDIM + akh : (const uint32_t*)0;

    const uint32_t a_sts = (uint32_t)(ar * 80 + akh * 2);
    const uint32_t bswz = (uint32_t)((bk & 7) * 16);
    const uint32_t b_base = (uint32_t)(BOFF1 + bmat * 4096 + bk * 128);
    const uint32_t b_sts0 = b_base + (((uint32_t)(bn * 2)) ^ bswz);
    const uint32_t b_sts1 = b_base + (((uint32_t)(bn * 2 + 16)) ^ bswz);

    uint4 pa[4], rb[2];
    float accG[2][4][4], accU[2][4][4];
#pragma unroll
    for (int i = 0; i < 2; i++)
#pragma unroll
        for (int j = 0; j < 4; j++)
#pragma unroll
            for (int q = 0; q < 4; q++) { accG[i][j][q] = 0.0f; accU[i][j][q] = 0.0f; }

#define G1_LDG(c) do { int k0 = (c) * 32;                                         \
        if (asrc) { pa[0] = *(const uint4*)(asrc + k0);                           \
                    pa[1] = *(const uint4*)(asrc + k0 + 4);                       \
                    pa[2] = *(const uint4*)(asrc + k0 + 8);                       \
                    pa[3] = *(const uint4*)(asrc + k0 + 12); }                    \
        else { pa[0] = make_uint4(0u,0u,0u,0u); pa[1]=pa[0]; pa[2]=pa[0]; pa[3]=pa[0]; } \
        const __half* bp = bsrc + (size_t)k0 * IDIM;                              \
        rb[0] = *(const uint4*)(bp);                                              \
        rb[1] = *(const uint4*)(bp + 8);                                          \
    } while (0)

#define G1_STS(stb) do {                                                          \
        uint32_t h[8], l[8];                                                      \
        h[0] = prmt32(pa[0].x, pa[0].y, 0x7632u); l[0] = prmt32(pa[0].x, pa[0].y, 0x5410u); \
        h[1] = prmt32(pa[0].z, pa[0].w, 0x7632u); l[1] = prmt32(pa[0].z, pa[0].w, 0x5410u); \
        h[2] = prmt32(pa[1].x, pa[1].y, 0x7632u); l[2] = prmt32(pa[1].x, pa[1].y, 0x5410u); \
        h[3] = prmt32(pa[1].z, pa[1].w, 0x7632u); l[3] = prmt32(pa[1].z, pa[1].w, 0x5410u); \
        h[4] = prmt32(pa[2].x, pa[2].y, 0x7632u); l[4] = prmt32(pa[2].x, pa[2].y, 0x5410u); \
        h[5] = prmt32(pa[2].z, pa[2].w, 0x7632u); l[5] = prmt32(pa[2].z, pa[2].w, 0x5410u); \
        h[6] = prmt32(pa[3].x, pa[3].y, 0x7632u); l[6] = prmt32(pa[3].x, pa[3].y, 0x5410u); \
        h[7] = prmt32(pa[3].z, pa[3].w, 0x7632u); l[7] = prmt32(pa[3].z, pa[3].w, 0x5410u); \
        sts4((stb) + a_sts,        h[0], h[1], h[2], h[3]);                       \
        sts4((stb) + a_sts + 16,   h[4], h[5], h[6], h[7]);                       \
        sts4((stb) + APL + a_sts,      l[0], l[1], l[2], l[3]);                   \
        sts4((stb) + APL + a_sts + 16, l[4], l[5], l[6], l[7]);                   \
        sts4((stb) + b_sts0, rb[0].x, rb[0].y, rb[0].z, rb[0].w);                 \
        sts4((stb) + b_sts1, rb[1].x, rb[1].y, rb[1].z, rb[1].w);                 \
    } while (0)

    G1_LDG(0);
    G1_STS(SB);
    __syncthreads();

    for (int c = 0; c < 64; c++) {
        uint32_t stb = SB + (uint32_t)(c & 1) * STAGE1;
        if (c < 63) G1_LDG(c + 1);
#pragma unroll
        for (int s = 0; s < 2; s++) {
            uint32_t aH[2][4], aL[2][4];
#pragma unroll
            for (int i = 0; i < 2; i++) {
                uint32_t ab = stb + (uint32_t)((wm + i * 16 + (lane & 15)) * 80 +
                                               ((lane >> 4) * 16) + s * 32);
                ldsm4(aH[i], ab);
                ldsm4(aL[i], ab + APL);
            }
            int krow = s * 16 + (lane & 15);
            uint32_t ksw = (uint32_t)((krow & 7) * 16);
            uint32_t rowb = (uint32_t)(krow * 128);
            uint32_t bf[2][4][2];
#pragma unroll
            for (int m = 0; m < 2; m++)
#pragma unroll
                for (int j2 = 0; j2 < 2; j2++) {
                    uint32_t chunk = (((uint32_t)((wn + j2 * 16) * 2 + (lane >> 4) * 16)) ^ ksw);
                    uint32_t r[4];
                    ldsm4t(r, stb + BOFF1 + (uint32_t)m * 4096 + rowb + chunk);
                    bf[m][j2 * 2][0] = r[0]; bf[m][j2 * 2][1] = r[1];
                    bf[m][j2 * 2 + 1][0] = r[2]; bf[m][j2 * 2 + 1][1] = r[3];
                }
#pragma unroll
            for (int i = 0; i < 2; i++)
#pragma unroll
                for (int j = 0; j < 4; j++) {
                    mma16816(accG[i][j], aH[i], bf[0][j]);
                    mma16816(accU[i][j], aH[i], bf[1][j]);
                }
#pragma unroll
            for (int i = 0; i < 2; i++)
#pragma unroll
                for (int j = 0; j < 4; j++) {
                    mma16816(accG[i][j], aL[i], bf[0][j]);
                    mma16816(accU[i][j], aL[i], bf[1][j]);
                }
        }
        if (c < 63) G1_STS(SB + (uint32_t)((c + 1) & 1) * STAGE1);
        __syncthreads();
    }

    // epilogue: silu(G)*U -> g_acth (fp16)
    int r0 = lane >> 2, cc = 2 * (lane & 3);
#pragma unroll
    for (int i = 0; i < 2; i++)
#pragma unroll
        for (int j = 0; j < 4; j++) {
            int col = n0 + wn + j * 8 + cc;
#pragma unroll
            for (int h = 0; h < 2; h++) {
                int row = row_start + wm + i * 16 + r0 + h * 8;
                float g0 = accG[i][j][2 * h],     u0 = accU[i][j][2 * h];
                float g1 = accG[i][j][2 * h + 1], u1 = accU[i][j][2 * h + 1];
                float a0 = (g0 / (1.0f + __expf(-g0))) * u0;
                float a1 = (g1 / (1.0f + __expf(-g1))) * u1;
                *(uint32_t*)&g_acth[(size_t)row * IDIM + col] = cvt2(a0, a1);
            }
        }
#undef G1_LDG
#undef G1_STS
}

// ---------------- GEMM2: HMMA fp16 single product, down + weighted scatter ---
// CTA: M=128, N=128, KC=32. 8 warps = 2(M) x 4(N), warp 64x32. 2 CTAs/SM.
__global__ __launch_bounds__(256, 2) void gemm2_kernel(float* __restrict__ out) {
    int e = g_tile_e[blockIdx.y];
    if (e < 0) return;
    int row_start = g_tile_row[blockIdx.y];
    int n0 = blockIdx.x * 128;
    extern __shared__ __align__(1024) char smem[];
    uint32_t SB = smem_u32(smem);

    const int tid = threadIdx.x;
    const int lane = tid & 31, wid = tid >> 5;
    const int wm = (wid & 1) * 64, wn = (wid >> 1) * 32;

    const int ar = tid >> 1;
    const int akh = (tid & 1) * 16;             // halfs
    const __half* asrc = g_acth + (size_t)(row_start + ar) * IDIM + akh;
    const int bk = tid >> 3;                    // 0..31
    const int bn = (tid & 7) * 16;              // halfs
    const __half* bsrc = g_w2h + (size_t)e * WMAT + (size_t)bk * HDIM + n0 + bn;

    const uint32_t a_sts = (uint32_t)(ar * 80 + akh * 2);
    const uint32_t bswz = (uint32_t)((bk & 7) * 16);
    const uint32_t b_base = (uint32_t)(BOFF2 + bk * 256);
    const uint32_t b_sts0 = b_base + (((uint32_t)(bn * 2)) ^ bswz);
    const uint32_t b_sts1 = b_base + (((uint32_t)(bn * 2 + 16)) ^ bswz);

    uint4 pa[2], rb[2];
    float acc[4][4][4];
#pragma unroll
    for (int i = 0; i < 4; i++)
#pragma unroll
        for (int j = 0; j < 4; j++)
#pragma unroll
            for (int q = 0; q < 4; q++) acc[i][j][q] = 0.0f;

#define G2_LDG(c) do { int k0 = (c) * 32;                                         \
        pa[0] = *(const uint4*)(asrc + k0);                                       \
        pa[1] = *(const uint4*)(asrc + k0 + 8);                                   \
        const __half* bp = bsrc + (size_t)k0 * HDIM;                              \
        rb[0] = *(const uint4*)(bp);                                              \
        rb[1] = *(const uint4*)(bp + 8);                                          \
    } while (0)

#define G2_STS(stb) do {                                                          \
        sts4((stb) + a_sts,      pa[0].x, pa[0].y, pa[0].z, pa[0].w);             \
        sts4((stb) + a_sts + 16, pa[1].x, pa[1].y, pa[1].z, pa[1].w);             \
        sts4((stb) + b_sts0, rb[0].x, rb[0].y, rb[0].z, rb[0].w);                 \
        sts4((stb) + b_sts1, rb[1].x, rb[1].y, rb[1].z, rb[1].w);                 \
    } while (0)

    G2_LDG(0);
    G2_STS(SB);
    __syncthreads();

    for (int c = 0; c < 64; c++) {
        uint32_t stb = SB + (uint32_t)(c & 1) * STAGE2;
        if (c < 63) G2_LDG(c + 1);
#pragma unroll
        for (int s = 0; s < 2; s++) {
            uint32_t aH[4][4];
#pragma unroll
            for (int i = 0; i < 4; i++) {
                uint32_t ab = stb + (uint32_t)((wm + i * 16 + (lane & 15)) * 80 +
                                               ((lane >> 4) * 16) + s * 32);
                ldsm4(aH[i], ab);
            }
            int krow = s * 16 + (lane & 15);
            uint32_t ksw = (uint32_t)((krow & 7) * 16);
            uint32_t rowb = (uint32_t)(krow * 256);
            uint32_t bf[4][2];
#pragma unroll
            for (int j2 = 0; j2 < 2; j2++) {
                uint32_t chunk = (((uint32_t)((wn + j2 * 16) * 2 + (lane >> 4) * 16)) ^ ksw);
                uint32_t r[4];
                ldsm4t(r, stb + BOFF2 + rowb + chunk);
                bf[j2 * 2][0] = r[0]; bf[j2 * 2][1] = r[1];
                bf[j2 * 2 + 1][0] = r[2]; bf[j2 * 2 + 1][1] = r[3];
            }
#pragma unroll
            for (int i = 0; i < 4; i++)
#pragma unroll
                for (int j = 0; j < 4; j++)
                    mma16816(acc[i][j], aH[i], bf[j]);
        }
        if (c < 63) G2_STS(SB + (uint32_t)((c + 1) & 1) * STAGE2);
        __syncthreads();
    }

    // epilogue: weighted atomic scatter-add (2 adds/elem total -> deterministic)
    int r0 = lane >> 2, cc = 2 * (lane & 3);
#pragma unroll
    for (int i = 0; i < 4; i++)
#pragma unroll
        for (int h = 0; h < 2; h++) {
            int row = row_start + wm + i * 16 + r0 + h * 8;
            int tok = g_row_token[row];
            if (tok < 0) continue;
            float w = g_row_weight[row];
            float* ob = out + (size_t)tok * HDIM + n0;
#pragma unroll
            for (int j = 0; j < 4; j++) {
                int col = wn + j * 8 + cc;
                atomicAdd(ob + col,     w * acc[i][j][2 * h]);
                atomicAdd(ob + col + 1, w * acc[i][j][2 * h + 1]);
            }
        }
#undef G2_LDG
#undef G2_STS
}

// ---------------- launch -----------------------------------------------------
extern "C" void kernel_launch(void* const* d_in, const int* in_sizes, int n_in,
                              void* d_out, int out_size) {
    const float* x  = (const float*)d_in[0];
    const float* gw = (const float*)d_in[1];
    const float* w1 = (const float*)d_in[2];
    const float* w3 = (const float*)d_in[3];
    const float* w2 = (const float*)d_in[4];
    float* out = (float*)d_out;

    static int attr_done = 0;
    if (!attr_done) {
        cudaFuncSetAttribute(gemm1_kernel, cudaFuncAttributeMaxDynamicSharedMemorySize, 2 * STAGE1);
        cudaFuncSetAttribute(gemm2_kernel, cudaFuncAttributeMaxDynamicSharedMemorySize, 2 * STAGE2);
        attr_done = 1;
    }

    reset_kernel<<<(T_TOK * HDIM + 255) / 256, 256>>>(out);
    router_kernel<<<T_TOK, 256>>>(x, gw);
    plan_kernel<<<1, 32>>>();
    scatter_kernel<<<(T_TOK + 255) / 256, 256>>>();
    prep_w_kernel<<<dim3(32768, 3), 256>>>(w1, w3, w2);
    prep_x_kernel<<<4096, 256>>>(x);

    gemm1_kernel<<<dim3(32, MAX_TILES), 256, 2 * STAGE1>>>();
    gemm2_kernel<<<dim3(16, MAX_TILES), 256, 2 * STAGE2>>>(out);
}

// round 9
// speedup vs baseline: 3.6375x; 1.1947x over previous
#include <cuda_runtime.h>
#include <cuda_fp16.h>
#include <cstdint>

#define T_TOK 2048
#define HDIM  2048
#define IDIM  2048
#define NEXP  8
#define ROWS_PAD 5120          // 40 tiles * 128
#define MAX_TILES 40
#define WMAT ((size_t)2048 * 2048)

// gemm1 stage: Ah 0..10239, Al 10240..20479, B(2 mats fp16) 20480..28671
#define APL    10240           // 128 rows * 80B (32 fp16 + 8B pad)
#define BOFF1  20480
#define STAGE1 28672
#define NSTG   3
// gemm2 stage: A 0..10239, B 10240..18431
#define BOFF2  10240
#define STAGE2 18432

// ---------------- device scratch ---------------------------------------------
__device__ __half   g_w1h[NEXP * WMAT];   // fp16 weights, same [E][K][N] layout
__device__ __half   g_w3h[NEXP * WMAT];
__device__ __half   g_w2h[NEXP * WMAT];
__device__ __half   g_xh[(size_t)T_TOK * HDIM];     // x hi fp16 plane
__device__ __half   g_xl[(size_t)T_TOK * HDIM];     // x lo fp16 plane
__device__ __half   g_acth[(size_t)ROWS_PAD * IDIM]; // silu(g)*u fp16
__device__ int   g_row_token[ROWS_PAD];
__device__ float g_row_weight[ROWS_PAD];
__device__ int   g_tok_e[2 * T_TOK];
__device__ float g_tok_w[2 * T_TOK];
__device__ int   g_counts[NEXP];
__device__ int   g_cursor[NEXP];
__device__ int   g_seg_start[NEXP];
__device__ int   g_tile_e[MAX_TILES];
__device__ int   g_tile_row[MAX_TILES];

// ---------------- helpers ----------------------------------------------------
__device__ __forceinline__ uint32_t smem_u32(const void* p) {
    return (uint32_t)__cvta_generic_to_shared(p);
}
__device__ __forceinline__ void mma16816(float* c, const uint32_t* a, const uint32_t* b) {
    asm volatile(
        "mma.sync.aligned.m16n8k16.row.col.f32.f16.f16.f32 "
        "{%0,%1,%2,%3}, {%4,%5,%6,%7}, {%8,%9}, {%0,%1,%2,%3};"
        : "+f"(c[0]), "+f"(c[1]), "+f"(c[2]), "+f"(c[3])
        : "r"(a[0]), "r"(a[1]), "r"(a[2]), "r"(a[3]), "r"(b[0]), "r"(b[1]));
}
__device__ __forceinline__ void ldsm4(uint32_t* r, uint32_t a) {
    asm volatile("ldmatrix.sync.aligned.m8n8.x4.shared.b16 {%0,%1,%2,%3}, [%4];"
        : "=r"(r[0]), "=r"(r[1]), "=r"(r[2]), "=r"(r[3]) : "r"(a));
}
__device__ __forceinline__ void ldsm4t(uint32_t* r, uint32_t a) {
    asm volatile("ldmatrix.sync.aligned.m8n8.x4.trans.shared.b16 {%0,%1,%2,%3}, [%4];"
        : "=r"(r[0]), "=r"(r[1]), "=r"(r[2]), "=r"(r[3]) : "r"(a));
}
// cp.async 16B; n = src bytes (0 -> zero-fill)
__device__ __forceinline__ void cpa16(uint32_t d, const void* s, uint32_t n) {
    asm volatile("cp.async.cg.shared.global [%0], [%1], 16, %2;"
                 :: "r"(d), "l"(s), "r"(n) : "memory");
}
__device__ __forceinline__ void cpa16(uint32_t d, const void* s) {
    asm volatile("cp.async.cg.shared.global [%0], [%1], 16;"
                 :: "r"(d), "l"(s) : "memory");
}
#define CP_COMMIT() asm volatile("cp.async.commit_group;" ::: "memory")
__device__ __forceinline__ uint32_t cvt2(float a, float b) {
    __half2 h = __floats2half2_rn(a, b);
    return *(uint32_t*)&h;
}

// ---------------- reset ------------------------------------------------------
__global__ void reset_kernel(float* __restrict__ out) {
    int idx = blockIdx.x * 256 + threadIdx.x;
    if (idx < T_TOK * HDIM) out[idx] = 0.0f;
    if (idx < ROWS_PAD) g_row_token[idx] = -1;
    if (idx < NEXP) { g_counts[idx] = 0; g_cursor[idx] = 0; }
}

// ---------------- router -----------------------------------------------------
__global__ __launch_bounds__(256) void router_kernel(const float* __restrict__ x,
                                                     const float* __restrict__ gw) {
    int t = blockIdx.x;
    const float* xr = x + (size_t)t * HDIM;
    float acc[NEXP];
#pragma unroll
    for (int e = 0; e < NEXP; e++) acc[e] = 0.0f;
    for (int h = threadIdx.x; h < HDIM; h += 256) {
        float xv = xr[h];
#pragma unroll
        for (int e = 0; e < NEXP; e++) acc[e] = fmaf(xv, gw[e * HDIM + h], acc[e]);
    }
#pragma unroll
    for (int off = 16; off > 0; off >>= 1)
#pragma unroll
        for (int e = 0; e < NEXP; e++)
            acc[e] += __shfl_down_sync(0xffffffffu, acc[e], off);

    __shared__ float red[8][NEXP];
    int wid = threadIdx.x >> 5, lane = threadIdx.x & 31;
    if (lane == 0)
#pragma unroll
        for (int e = 0; e < NEXP; e++) red[wid][e] = acc[e];
    __syncthreads();

    if (threadIdx.x == 0) {
        float l[NEXP];
#pragma unroll
        for (int e = 0; e < NEXP; e++) {
            float s = 0.0f;
#pragma unroll
            for (int w = 0; w < 8; w++) s += red[w][e];
            l[e] = s;
        }
        int i0 = 0;
#pragma unroll
        for (int e = 1; e < NEXP; e++) if (l[e] > l[i0]) i0 = e;
        int i1 = -1;
#pragma unroll
        for (int e = 0; e < NEXP; e++)
            if (e != i0 && (i1 < 0 || l[e] > l[i1])) i1 = e;
        float w0 = 1.0f / (1.0f + expf(l[i1] - l[i0]));
        float w1 = 1.0f - w0;
        g_tok_e[2 * t] = i0;     g_tok_e[2 * t + 1] = i1;
        g_tok_w[2 * t] = w0;     g_tok_w[2 * t + 1] = w1;
        atomicAdd(&g_counts[i0], 1);
        atomicAdd(&g_counts[i1], 1);
    }
}

// ---------------- plan + scatter ---------------------------------------------
__global__ void plan_kernel() {
    if (threadIdx.x != 0) return;
    int off = 0, tile = 0;
    for (int e = 0; e < NEXP; e++) {
        g_seg_start[e] = off;
        int n = g_counts[e];
        int nt = (n + 127) >> 7;
        for (int j = 0; j < nt; j++) { g_tile_e[tile] = e; g_tile_row[tile] = off + (j << 7); tile++; }
        off += nt << 7;
    }
    for (; tile < MAX_TILES; tile++) g_tile_e[tile] = -1;
}

__global__ void scatter_kernel() {
    int t = blockIdx.x * 256 + threadIdx.x;
    if (t >= T_TOK) return;
#pragma unroll
    for (int k = 0; k < 2; k++) {
        int e = g_tok_e[2 * t + k];
        int r = atomicAdd(&g_cursor[e], 1);
        int row = g_seg_start[e] + r;
        g_row_token[row] = t;
        g_row_weight[row] = g_tok_w[2 * t + k];
    }
}

// ---------------- prep: weights fp32 -> fp16, x fp32 -> hi/lo planes ---------
__global__ __launch_bounds__(256) void prep_w_kernel(const float* __restrict__ w1,
                                                     const float* __restrict__ w3,
                                                     const float* __restrict__ w2) {
    int mat = blockIdx.y;
    const float* src = (mat == 0 ? w1 : (mat == 1 ? w3 : w2));
    __half* dst = (mat == 0 ? g_w1h : (mat == 1 ? g_w3h : g_w2h));
    size_t i = ((size_t)blockIdx.x * 256 + threadIdx.x);
    float4 v = *(const float4*)(src + 4 * i);
    uint2 o;
    o.x = cvt2(v.x, v.y);
    o.y = cvt2(v.z, v.w);
    *(uint2*)(dst + 4 * i) = o;
}

__global__ __launch_bounds__(256) void prep_x_kernel(const float* __restrict__ x) {
    size_t i = ((size_t)blockIdx.x * 256 + threadIdx.x);
    float4 v = *(const float4*)(x + 4 * i);
    __half h0 = __float2half_rn(v.x), h1 = __float2half_rn(v.y);
    __half h2 = __float2half_rn(v.z), h3 = __float2half_rn(v.w);
    uint2 hi, lo;
    hi.x = ((uint32_t)__half_as_ushort(h1) << 16) | __half_as_ushort(h0);
    hi.y = ((uint32_t)__half_as_ushort(h3) << 16) | __half_as_ushort(h2);
    lo.x = cvt2(v.x - __half2float(h0), v.y - __half2float(h1));
    lo.y = cvt2(v.z - __half2float(h2), v.w - __half2float(h3));
    *(uint2*)(g_xh + 4 * i) = hi;
    *(uint2*)(g_xl + 4 * i) = lo;
}

// ---------------- GEMM1: HMMA fp16 A-split-2, cp.async 3-stage ---------------
// CTA: M=128, N=64 (per mat), KC=32. 8 warps = 4(M) x 2(N), warp 32x32, dual acc.
__global__ __launch_bounds__(256, 2) void gemm1_kernel() {
    int e = g_tile_e[blockIdx.y];
    if (e < 0) return;
    int row_start = g_tile_row[blockIdx.y];
    int n0 = blockIdx.x * 64;
    extern __shared__ __align__(1024) char smem[];
    uint32_t SB = smem_u32(smem);

    const int tid = threadIdx.x;
    const int lane = tid & 31, wid = tid >> 5;
    const int wm = (wid & 3) * 32, wn = (wid >> 2) * 32;

    // staging maps
    const int bmat = tid >> 7;                  // 0:w1  1:w3
    const int bk = (tid & 127) >> 2;            // 0..31
    const int bn = (tid & 3) * 16;              // half col offset
    const __half* bsrc = (bmat ? g_w3h : g_w1h) + (size_t)e * WMAT + (size_t)bk * IDIM + n0 + bn;
    const int ar = tid >> 1;                    // 0..127
    const int akh = (tid & 1) * 16;             // K elems
    int tok0 = g_row_token[row_start + ar];
    const uint32_t asz = (tok0 >= 0) ? 16u : 0u;
    const __half* axh = (tok0 >= 0) ? g_xh + (size_t)tok0 * HDIM + akh : g_xh;
    const __half* axl = (tok0 >= 0) ? g_xl + (size_t)tok0 * HDIM + akh : g_xl;

    const uint32_t a_sts = (uint32_t)(ar * 80 + akh * 2);
    const uint32_t bswz = (uint32_t)((bk & 7) * 16);
    const uint32_t b_base = (uint32_t)(BOFF1 + bmat * 4096 + bk * 128);
    const uint32_t b_sts0 = b_base + (((uint32_t)(bn * 2)) ^ bswz);
    const uint32_t b_sts1 = b_base + (((uint32_t)(bn * 2 + 16)) ^ bswz);

    float accG[2][4][4], accU[2][4][4];
#pragma unroll
    for (int i = 0; i < 2; i++)
#pragma unroll
        for (int j = 0; j < 4; j++)
#pragma unroll
            for (int q = 0; q < 4; q++) { accG[i][j][q] = 0.0f; accU[i][j][q] = 0.0f; }

#define G1_ISSUE(ch, slot) do {                                                   \
        uint32_t stb = SB + (uint32_t)(slot) * STAGE1;                            \
        int k0 = (ch) * 32;                                                       \
        cpa16(stb + a_sts,            axh + k0,     asz);                         \
        cpa16(stb + a_sts + 16,       axh + k0 + 8, asz);                         \
        cpa16(stb + APL + a_sts,      axl + k0,     asz);                         \
        cpa16(stb + APL + a_sts + 16, axl + k0 + 8, asz);                         \
        const __half* bp = bsrc + (size_t)k0 * IDIM;                              \
        cpa16(stb + b_sts0, bp);                                                  \
        cpa16(stb + b_sts1, bp + 8);                                              \
        CP_COMMIT();                                                              \
    } while (0)

    G1_ISSUE(0, 0);
    G1_ISSUE(1, 1);

    for (int c = 0; c < 64; c++) {
        if (c < 63) asm volatile("cp.async.wait_group 1;" ::: "memory");
        else        asm volatile("cp.async.wait_group 0;" ::: "memory");
        __syncthreads();
        if (c + 2 < 64) G1_ISSUE(c + 2, (c + 2) % NSTG);

        uint32_t stb = SB + (uint32_t)(c % NSTG) * STAGE1;
#pragma unroll
        for (int s = 0; s < 2; s++) {
            uint32_t aH[2][4], aL[2][4];
#pragma unroll
            for (int i = 0; i < 2; i++) {
                uint32_t ab = stb + (uint32_t)((wm + i * 16 + (lane & 15)) * 80 +
                                               ((lane >> 4) * 16) + s * 32);
                ldsm4(aH[i], ab);
                ldsm4(aL[i], ab + APL);
            }
            int krow = s * 16 + (lane & 15);
            uint32_t ksw = (uint32_t)((krow & 7) * 16);
            uint32_t rowb = (uint32_t)(krow * 128);
            uint32_t bf[2][4][2];
#pragma unroll
            for (int m = 0; m < 2; m++)
#pragma unroll
                for (int j2 = 0; j2 < 2; j2++) {
                    uint32_t chunk = (((uint32_t)((wn + j2 * 16) * 2 + (lane >> 4) * 16)) ^ ksw);
                    uint32_t r[4];
                    ldsm4t(r, stb + BOFF1 + (uint32_t)m * 4096 + rowb + chunk);
                    bf[m][j2 * 2][0] = r[0]; bf[m][j2 * 2][1] = r[1];
                    bf[m][j2 * 2 + 1][0] = r[2]; bf[m][j2 * 2 + 1][1] = r[3];
                }
#pragma unroll
            for (int i = 0; i < 2; i++)
#pragma unroll
                for (int j = 0; j < 4; j++) {
                    mma16816(accG[i][j], aH[i], bf[0][j]);
                    mma16816(accU[i][j], aH[i], bf[1][j]);
                }
#pragma unroll
            for (int i = 0; i < 2; i++)
#pragma unroll
                for (int j = 0; j < 4; j++) {
                    mma16816(accG[i][j], aL[i], bf[0][j]);
                    mma16816(accU[i][j], aL[i], bf[1][j]);
                }
        }
    }

    // epilogue: silu(G)*U -> g_acth (fp16)
    int r0 = lane >> 2, cc = 2 * (lane & 3);
#pragma unroll
    for (int i = 0; i < 2; i++)
#pragma unroll
        for (int j = 0; j < 4; j++) {
            int col = n0 + wn + j * 8 + cc;
#pragma unroll
            for (int h = 0; h < 2; h++) {
                int row = row_start + wm + i * 16 + r0 + h * 8;
                float g0 = accG[i][j][2 * h],     u0 = accU[i][j][2 * h];
                float g1 = accG[i][j][2 * h + 1], u1 = accU[i][j][2 * h + 1];
                float a0 = (g0 / (1.0f + __expf(-g0))) * u0;
                float a1 = (g1 / (1.0f + __expf(-g1))) * u1;
                *(uint32_t*)&g_acth[(size_t)row * IDIM + col] = cvt2(a0, a1);
            }
        }
#undef G1_ISSUE
}

// ---------------- GEMM2: HMMA fp16 single product, cp.async 3-stage ----------
// CTA: M=128, N=128, KC=32. 8 warps = 2(M) x 4(N), warp 64x32. 2 CTAs/SM.
__global__ __launch_bounds__(256, 2) void gemm2_kernel(float* __restrict__ out) {
    int e = g_tile_e[blockIdx.y];
    if (e < 0) return;
    int row_start = g_tile_row[blockIdx.y];
    int n0 = blockIdx.x * 128;
    extern __shared__ __align__(1024) char smem[];
    uint32_t SB = smem_u32(smem);

    const int tid = threadIdx.x;
    const int lane = tid & 31, wid = tid >> 5;
    const int wm = (wid & 1) * 64, wn = (wid >> 1) * 32;

    const int ar = tid >> 1;
    const int akh = (tid & 1) * 16;             // halfs
    const __half* asrc = g_acth + (size_t)(row_start + ar) * IDIM + akh;
    const int bk = tid >> 3;                    // 0..31
    const int bn = (tid & 7) * 16;              // halfs
    const __half* bsrc = g_w2h + (size_t)e * WMAT + (size_t)bk * HDIM + n0 + bn;

    const uint32_t a_sts = (uint32_t)(ar * 80 + akh * 2);
    const uint32_t bswz = (uint32_t)((bk & 7) * 16);
    const uint32_t b_base = (uint32_t)(BOFF2 + bk * 256);
    const uint32_t b_sts0 = b_base + (((uint32_t)(bn * 2)) ^ bswz);
    const uint32_t b_sts1 = b_base + (((uint32_t)(bn * 2 + 16)) ^ bswz);

    float acc[4][4][4];
#pragma unroll
    for (int i = 0; i < 4; i++)
#pragma unroll
        for (int j = 0; j < 4; j++)
#pragma unroll
            for (int q = 0; q < 4; q++) acc[i][j][q] = 0.0f;

#define G2_ISSUE(ch, slot) do {                                                   \
        uint32_t stb = SB + (uint32_t)(slot) * STAGE2;                            \
        int k0 = (ch) * 32;                                                       \
        cpa16(stb + a_sts,      asrc + k0);                                       \
        cpa16(stb + a_sts + 16, asrc + k0 + 8);                                   \
        const __half* bp = bsrc + (size_t)k0 * HDIM;                              \
        cpa16(stb + b_sts0, bp);                                                  \
        cpa16(stb + b_sts1, bp + 8);                                              \
        CP_COMMIT();                                                              \
    } while (0)

    G2_ISSUE(0, 0);
    G2_ISSUE(1, 1);

    for (int c = 0; c < 64; c++) {
        if (c < 63) asm volatile("cp.async.wait_group 1;" ::: "memory");
        else        asm volatile("cp.async.wait_group 0;" ::: "memory");
        __syncthreads();
        if (c + 2 < 64) G2_ISSUE(c + 2, (c + 2) % NSTG);

        uint32_t stb = SB + (uint32_t)(c % NSTG) * STAGE2;
#pragma unroll
        for (int s = 0; s < 2; s++) {
            uint32_t aH[4][4];
#pragma unroll
            for (int i = 0; i < 4; i++) {
                uint32_t ab = stb + (uint32_t)((wm + i * 16 + (lane & 15)) * 80 +
                                               ((lane >> 4) * 16) + s * 32);
                ldsm4(aH[i], ab);
            }
            int krow = s * 16 + (lane & 15);
            uint32_t ksw = (uint32_t)((krow & 7) * 16);
            uint32_t rowb = (uint32_t)(krow * 256);
            uint32_t bf[4][2];
#pragma unroll
            for (int j2 = 0; j2 < 2; j2++) {
                uint32_t chunk = (((uint32_t)((wn + j2 * 16) * 2 + (lane >> 4) * 16)) ^ ksw);
                uint32_t r[4];
                ldsm4t(r, stb + BOFF2 + rowb + chunk);
                bf[j2 * 2][0] = r[0]; bf[j2 * 2][1] = r[1];
                bf[j2 * 2 + 1][0] = r[2]; bf[j2 * 2 + 1][1] = r[3];
            }
#pragma unroll
            for (int i = 0; i < 4; i++)
#pragma unroll
                for (int j = 0; j < 4; j++)
                    mma16816(acc[i][j], aH[i], bf[j]);
        }
    }

    // epilogue: weighted atomic scatter-add (2 adds/elem total -> deterministic)
    int r0 = lane >> 2, cc = 2 * (lane & 3);
#pragma unroll
    for (int i = 0; i < 4; i++)
#pragma unroll
        for (int h = 0; h < 2; h++) {
            int row = row_start + wm + i * 16 + r0 + h * 8;
            int tok = g_row_token[row];
            if (tok < 0) continue;
            float w = g_row_weight[row];
            float* ob = out + (size_t)tok * HDIM + n0;
#pragma unroll
            for (int j = 0; j < 4; j++) {
                int col = wn + j * 8 + cc;
                atomicAdd(ob + col,     w * acc[i][j][2 * h]);
                atomicAdd(ob + col + 1, w * acc[i][j][2 * h + 1]);
            }
        }
#undef G2_ISSUE
}

// ---------------- launch -----------------------------------------------------
extern "C" void kernel_launch(void* const* d_in, const int* in_sizes, int n_in,
                              void* d_out, int out_size) {
    const float* x  = (const float*)d_in[0];
    const float* gw = (const float*)d_in[1];
    const float* w1 = (const float*)d_in[2];
    const float* w3 = (const float*)d_in[3];
    const float* w2 = (const float*)d_in[4];
    float* out = (float*)d_out;

    static int attr_done = 0;
    if (!attr_done) {
        cudaFuncSetAttribute(gemm1_kernel, cudaFuncAttributeMaxDynamicSharedMemorySize, NSTG * STAGE1);
        cudaFuncSetAttribute(gemm2_kernel, cudaFuncAttributeMaxDynamicSharedMemorySize, NSTG * STAGE2);
        attr_done = 1;
    }

    reset_kernel<<<(T_TOK * HDIM + 255) / 256, 256>>>(out);
    router_kernel<<<T_TOK, 256>>>(x, gw);
    plan_kernel<<<1, 32>>>();
    scatter_kernel<<<(T_TOK + 255) / 256, 256>>>();
    prep_w_kernel<<<dim3(32768, 3), 256>>>(w1, w3, w2);
    prep_x_kernel<<<4096, 256>>>(x);

    gemm1_kernel<<<dim3(32, MAX_TILES), 256, NSTG * STAGE1>>>();
    gemm2_kernel<<<dim3(16, MAX_TILES), 256, NSTG * STAGE2>>>(out);
}

// round 12
// speedup vs baseline: 5.0184x; 1.3796x over previous
#include <cuda_runtime.h>
#include <cuda_fp16.h>
#include <cstdint>

#define T_TOK 2048
#define HDIM  2048
#define IDIM  2048
#define NEXP  8
#define ROWS_PAD 5120          // 40 tiles * 128
#define MAX_TILES 40
#define WMAT ((size_t)2048 * 2048)

// both GEMM stages: A 0..10239 (128 rows * 80B), B at 10240..18431
#define APITCH 80
#define BOFF   10240
#define STAGE  18432
#define NSTG   3

// ---------------- device scratch ---------------------------------------------
__device__ __half   g_w1h[NEXP * WMAT];   // fp16 weights, same [E][K][N] layout
__device__ __half   g_w3h[NEXP * WMAT];
__device__ __half   g_w2h[NEXP * WMAT];
__device__ __half   g_xh[(size_t)T_TOK * HDIM];     // x fp16
__device__ __half   g_acth[(size_t)ROWS_PAD * IDIM]; // silu(g)*u fp16
__device__ int   g_row_token[ROWS_PAD];
__device__ float g_row_weight[ROWS_PAD];
__device__ int   g_tok_e[2 * T_TOK];
__device__ float g_tok_w[2 * T_TOK];
__device__ int   g_counts[NEXP];
__device__ int   g_cursor[NEXP];
__device__ int   g_seg_start[NEXP];
__device__ int   g_tile_e[MAX_TILES];
__device__ int   g_tile_row[MAX_TILES];

// ---------------- helpers ----------------------------------------------------
__device__ __forceinline__ uint32_t smem_u32(const void* p) {
    return (uint32_t)__cvta_generic_to_shared(p);
}
__device__ __forceinline__ void mma16816(float* c, const uint32_t* a, const uint32_t* b) {
    asm volatile(
        "mma.sync.aligned.m16n8k16.row.col.f32.f16.f16.f32 "
        "{%0,%1,%2,%3}, {%4,%5,%6,%7}, {%8,%9}, {%0,%1,%2,%3};"
        : "+f"(c[0]), "+f"(c[1]), "+f"(c[2]), "+f"(c[3])
        : "r"(a[0]), "r"(a[1]), "r"(a[2]), "r"(a[3]), "r"(b[0]), "r"(b[1]));
}
__device__ __forceinline__ void ldsm4(uint32_t* r, uint32_t a) {
    asm volatile("ldmatrix.sync.aligned.m8n8.x4.shared.b16 {%0,%1,%2,%3}, [%4];"
        : "=r"(r[0]), "=r"(r[1]), "=r"(r[2]), "=r"(r[3]) : "r"(a));
}
__device__ __forceinline__ void ldsm4t(uint32_t* r, uint32_t a) {
    asm volatile("ldmatrix.sync.aligned.m8n8.x4.trans.shared.b16 {%0,%1,%2,%3}, [%4];"
        : "=r"(r[0]), "=r"(r[1]), "=r"(r[2]), "=r"(r[3]) : "r"(a));
}
// cp.async 16B; n = src bytes (0 -> zero-fill)
__device__ __forceinline__ void cpa16(uint32_t d, const void* s, uint32_t n) {
    asm volatile("cp.async.cg.shared.global [%0], [%1], 16, %2;"
                 :: "r"(d), "l"(s), "r"(n) : "memory");
}
__device__ __forceinline__ void cpa16(uint32_t d, const void* s) {
    asm volatile("cp.async.cg.shared.global [%0], [%1], 16;"
                 :: "r"(d), "l"(s) : "memory");
}
#define CP_COMMIT() asm volatile("cp.async.commit_group;" ::: "memory")
__device__ __forceinline__ uint32_t cvt2(float a, float b) {
    __half2 h = __floats2half2_rn(a, b);
    return *(uint32_t*)&h;
}

// ---------------- reset ------------------------------------------------------
__global__ void reset_kernel(float* __restrict__ out) {
    int idx = blockIdx.x * 256 + threadIdx.x;
    if (idx < T_TOK * HDIM) out[idx] = 0.0f;
    if (idx < ROWS_PAD) g_row_token[idx] = -1;
    if (idx < NEXP) { g_counts[idx] = 0; g_cursor[idx] = 0; }
}

// ---------------- router -----------------------------------------------------
__global__ __launch_bounds__(256) void router_kernel(const float* __restrict__ x,
                                                     const float* __restrict__ gw) {
    int t = blockIdx.x;
    const float* xr = x + (size_t)t * HDIM;
    float acc[NEXP];
#pragma unroll
    for (int e = 0; e < NEXP; e++) acc[e] = 0.0f;
    for (int h = threadIdx.x; h < HDIM; h += 256) {
        float xv = xr[h];
#pragma unroll
        for (int e = 0; e < NEXP; e++) acc[e] = fmaf(xv, gw[e * HDIM + h], acc[e]);
    }
#pragma unroll
    for (int off = 16; off > 0; off >>= 1)
#pragma unroll
        for (int e = 0; e < NEXP; e++)
            acc[e] += __shfl_down_sync(0xffffffffu, acc[e], off);

    __shared__ float red[8][NEXP];
    int wid = threadIdx.x >> 5, lane = threadIdx.x & 31;
    if (lane == 0)
#pragma unroll
        for (int e = 0; e < NEXP; e++) red[wid][e] = acc[e];
    __syncthreads();

    if (threadIdx.x == 0) {
        float l[NEXP];
#pragma unroll
        for (int e = 0; e < NEXP; e++) {
            float s = 0.0f;
#pragma unroll
            for (int w = 0; w < 8; w++) s += red[w][e];
            l[e] = s;
        }
        int i0 = 0;
#pragma unroll
        for (int e = 1; e < NEXP; e++) if (l[e] > l[i0]) i0 = e;
        int i1 = -1;
#pragma unroll
        for (int e = 0; e < NEXP; e++)
            if (e != i0 && (i1 < 0 || l[e] > l[i1])) i1 = e;
        float w0 = 1.0f / (1.0f + expf(l[i1] - l[i0]));
        float w1 = 1.0f - w0;
        g_tok_e[2 * t] = i0;     g_tok_e[2 * t + 1] = i1;
        g_tok_w[2 * t] = w0;     g_tok_w[2 * t + 1] = w1;
        atomicAdd(&g_counts[i0], 1);
        atomicAdd(&g_counts[i1], 1);
    }
}

// ---------------- plan + scatter ---------------------------------------------
__global__ void plan_kernel() {
    if (threadIdx.x != 0) return;
    int off = 0, tile = 0;
    for (int e = 0; e < NEXP; e++) {
        g_seg_start[e] = off;
        int n = g_counts[e];
        int nt = (n + 127) >> 7;
        for (int j = 0; j < nt; j++) { g_tile_e[tile] = e; g_tile_row[tile] = off + (j << 7); tile++; }
        off += nt << 7;
    }
    for (; tile < MAX_TILES; tile++) g_tile_e[tile] = -1;
}

__global__ void scatter_kernel() {
    int t = blockIdx.x * 256 + threadIdx.x;
    if (t >= T_TOK) return;
#pragma unroll
    for (int k = 0; k < 2; k++) {
        int e = g_tok_e[2 * t + k];
        int r = atomicAdd(&g_cursor[e], 1);
        int row = g_seg_start[e] + r;
        g_row_token[row] = t;
        g_row_weight[row] = g_tok_w[2 * t + k];
    }
}

// ---------------- prep: weights + x fp32 -> fp16 -----------------------------
__global__ __launch_bounds__(256) void prep_w_kernel(const float* __restrict__ w1,
                                                     const float* __restrict__ w3,
                                                     const float* __restrict__ w2) {
    int mat = blockIdx.y;
    const float* src = (mat == 0 ? w1 : (mat == 1 ? w3 : w2));
    __half* dst = (mat == 0 ? g_w1h : (mat == 1 ? g_w3h : g_w2h));
    size_t i = ((size_t)blockIdx.x * 256 + threadIdx.x);
    float4 v = *(const float4*)(src + 4 * i);
    uint2 o;
    o.x = cvt2(v.x, v.y);
    o.y = cvt2(v.z, v.w);
    *(uint2*)(dst + 4 * i) = o;
}

__global__ __launch_bounds__(256) void prep_x_kernel(const float* __restrict__ x) {
    size_t i = ((size_t)blockIdx.x * 256 + threadIdx.x);
    float4 v = *(const float4*)(x + 4 * i);
    uint2 hi;
    hi.x = cvt2(v.x, v.y);
    hi.y = cvt2(v.z, v.w);
    *(uint2*)(g_xh + 4 * i) = hi;
}

// ---------------- GEMM1: HMMA fp16 single-product, fused gate+up + SiLU ------
// CTA: M=128, N=64 (per mat), KC=32. 8 warps = 4(M) x 2(N), warp 32x32, dual acc.
__global__ __launch_bounds__(256, 2) void gemm1_kernel() {
    int e = g_tile_e[blockIdx.y];
    if (e < 0) return;
    int row_start = g_tile_row[blockIdx.y];
    int n0 = blockIdx.x * 64;
    extern __shared__ __align__(1024) char smem[];
    uint32_t SB = smem_u32(smem);

    const int tid = threadIdx.x;
    const int lane = tid & 31, wid = tid >> 5;
    const int wm = (wid & 3) * 32, wn = (wid >> 2) * 32;

    // staging maps
    const int bmat = tid >> 7;                  // 0:w1  1:w3
    const int bk = (tid & 127) >> 2;            // 0..31
    const int bn = (tid & 3) * 16;              // half col offset
    const __half* bsrc = (bmat ? g_w3h : g_w1h) + (size_t)e * WMAT + (size_t)bk * IDIM + n0 + bn;
    const int ar = tid >> 1;                    // 0..127
    const int akh = (tid & 1) * 16;             // K elems
    int tok0 = g_row_token[row_start + ar];
    const uint32_t asz = (tok0 >= 0) ? 16u : 0u;
    const __half* axh = (tok0 >= 0) ? g_xh + (size_t)tok0 * HDIM + akh : g_xh;

    const uint32_t a_sts = (uint32_t)(ar * APITCH + akh * 2);
    const uint32_t bswz = (uint32_t)((bk & 7) * 16);
    const uint32_t b_base = (uint32_t)(BOFF + bmat * 4096 + bk * 128);
    const uint32_t b_sts0 = b_base + (((uint32_t)(bn * 2)) ^ bswz);
    const uint32_t b_sts1 = b_base + (((uint32_t)(bn * 2 + 16)) ^ bswz);

    float accG[2][4][4], accU[2][4][4];
#pragma unroll
    for (int i = 0; i < 2; i++)
#pragma unroll
        for (int j = 0; j < 4; j++)
#pragma unroll
            for (int q = 0; q < 4; q++) { accG[i][j][q] = 0.0f; accU[i][j][q] = 0.0f; }

#define G1_ISSUE(ch, slot) do {                                                   \
        uint32_t stb = SB + (uint32_t)(slot) * STAGE;                             \
        int k0 = (ch) * 32;                                                       \
        cpa16(stb + a_sts,      axh + k0,     asz);                               \
        cpa16(stb + a_sts + 16, axh + k0 + 8, asz);                               \
        const __half* bp = bsrc + (size_t)k0 * IDIM;                              \
        cpa16(stb + b_sts0, bp);                                                  \
        cpa16(stb + b_sts1, bp + 8);                                              \
        CP_COMMIT();                                                              \
    } while (0)

    G1_ISSUE(0, 0);
    G1_ISSUE(1, 1);

    for (int c = 0; c < 64; c++) {
        if (c < 63) asm volatile("cp.async.wait_group 1;" ::: "memory");
        else        asm volatile("cp.async.wait_group 0;" ::: "memory");
        __syncthreads();
        if (c + 2 < 64) G1_ISSUE(c + 2, (c + 2) % NSTG);

        uint32_t stb = SB + (uint32_t)(c % NSTG) * STAGE;
#pragma unroll
        for (int s = 0; s < 2; s++) {
            uint32_t aH[2][4];
#pragma unroll
            for (int i = 0; i < 2; i++) {
                uint32_t ab = stb + (uint32_t)((wm + i * 16 + (lane & 15)) * APITCH +
                                               ((lane >> 4) * 16) + s * 32);
                ldsm4(aH[i], ab);
            }
            int krow = s * 16 + (lane & 15);
            uint32_t ksw = (uint32_t)((krow & 7) * 16);
            uint32_t rowb = (uint32_t)(krow * 128);
            uint32_t bf[2][4][2];
#pragma unroll
            for (int m = 0; m < 2; m++)
#pragma unroll
                for (int j2 = 0; j2 < 2; j2++) {
                    uint32_t chunk = (((uint32_t)((wn + j2 * 16) * 2 + (lane >> 4) * 16)) ^ ksw);
                    uint32_t r[4];
                    ldsm4t(r, stb + BOFF + (uint32_t)m * 4096 + rowb + chunk);
                    bf[m][j2 * 2][0] = r[0]; bf[m][j2 * 2][1] = r[1];
                    bf[m][j2 * 2 + 1][0] = r[2]; bf[m][j2 * 2 + 1][1] = r[3];
                }
#pragma unroll
            for (int i = 0; i < 2; i++)
#pragma unroll
                for (int j = 0; j < 4; j++) {
                    mma16816(accG[i][j], aH[i], bf[0][j]);
                    mma16816(accU[i][j], aH[i], bf[1][j]);
                }
        }
    }

    // epilogue: silu(G)*U -> g_acth (fp16)
    int r0 = lane >> 2, cc = 2 * (lane & 3);
#pragma unroll
    for (int i = 0; i < 2; i++)
#pragma unroll
        for (int j = 0; j < 4; j++) {
            int col = n0 + wn + j * 8 + cc;
#pragma unroll
            for (int h = 0; h < 2; h++) {
                int row = row_start + wm + i * 16 + r0 + h * 8;
                float g0 = accG[i][j][2 * h],     u0 = accU[i][j][2 * h];
                float g1 = accG[i][j][2 * h + 1], u1 = accU[i][j][2 * h + 1];
                float a0 = (g0 / (1.0f + __expf(-g0))) * u0;
                float a1 = (g1 / (1.0f + __expf(-g1))) * u1;
                *(uint32_t*)&g_acth[(size_t)row * IDIM + col] = cvt2(a0, a1);
            }
        }
#undef G1_ISSUE
}

// ---------------- GEMM2: HMMA fp16 single product, cp.async 3-stage ----------
// CTA: M=128, N=128, KC=32. 8 warps = 2(M) x 4(N), warp 64x32. 2 CTAs/SM.
__global__ __launch_bounds__(256, 2) void gemm2_kernel(float* __restrict__ out) {
    int e = g_tile_e[blockIdx.y];
    if (e < 0) return;
    int row_start = g_tile_row[blockIdx.y];
    int n0 = blockIdx.x * 128;
    extern __shared__ __align__(1024) char smem[];
    uint32_t SB = smem_u32(smem);

    const int tid = threadIdx.x;
    const int lane = tid & 31, wid = tid >> 5;
    const int wm = (wid & 1) * 64, wn = (wid >> 1) * 32;

    const int ar = tid >> 1;
    const int akh = (tid & 1) * 16;             // halfs
    const __half* asrc = g_acth + (size_t)(row_start + ar) * IDIM + akh;
    const int bk = tid >> 3;                    // 0..31
    const int bn = (tid & 7) * 16;              // halfs
    const __half* bsrc = g_w2h + (size_t)e * WMAT + (size_t)bk * HDIM + n0 + bn;

    const uint32_t a_sts = (uint32_t)(ar * APITCH + akh * 2);
    const uint32_t bswz = (uint32_t)((bk & 7) * 16);
    const uint32_t b_base = (uint32_t)(BOFF + bk * 256);
    const uint32_t b_sts0 = b_base + (((uint32_t)(bn * 2)) ^ bswz);
    const uint32_t b_sts1 = b_base + (((uint32_t)(bn * 2 + 16)) ^ bswz);

    float acc[4][4][4];
#pragma unroll
    for (int i = 0; i < 4; i++)
#pragma unroll
        for (int j = 0; j < 4; j++)
#pragma unroll
            for (int q = 0; q < 4; q++) acc[i][j][q] = 0.0f;

#define G2_ISSUE(ch, slot) do {                                                   \
        uint32_t stb = SB + (uint32_t)(slot) * STAGE;                             \
        int k0 = (ch) * 32;                                                       \
        cpa16(stb + a_sts,      asrc + k0);                                       \
        cpa16(stb + a_sts + 16, asrc + k0 + 8);                                   \
        const __half* bp = bsrc + (size_t)k0 * HDIM;                              \
        cpa16(stb + b_sts0, bp);                                                  \
        cpa16(stb + b_sts1, bp + 8);                                              \
        CP_COMMIT();                                                              \
    } while (0)

    G2_ISSUE(0, 0);
    G2_ISSUE(1, 1);

    for (int c = 0; c < 64; c++) {
        if (c < 63) asm volatile("cp.async.wait_group 1;" ::: "memory");
        else        asm volatile("cp.async.wait_group 0;" ::: "memory");
        __syncthreads();
        if (c + 2 < 64) G2_ISSUE(c + 2, (c + 2) % NSTG);

        uint32_t stb = SB + (uint32_t)(c % NSTG) * STAGE;
#pragma unroll
        for (int s = 0; s < 2; s++) {
            uint32_t aH[4][4];
#pragma unroll
            for (int i = 0; i < 4; i++) {
                uint32_t ab = stb + (uint32_t)((wm + i * 16 + (lane & 15)) * APITCH +
                                               ((lane >> 4) * 16) + s * 32);
                ldsm4(aH[i], ab);
            }
            int krow = s * 16 + (lane & 15);
            uint32_t ksw = (uint32_t)((krow & 7) * 16);
            uint32_t rowb = (uint32_t)(krow * 256);
            uint32_t bf[4][2];
#pragma unroll
            for (int j2 = 0; j2 < 2; j2++) {
                uint32_t chunk = (((uint32_t)((wn + j2 * 16) * 2 + (lane >> 4) * 16)) ^ ksw);
                uint32_t r[4];
                ldsm4t(r, stb + BOFF + rowb + chunk);
                bf[j2 * 2][0] = r[0]; bf[j2 * 2][1] = r[1];
                bf[j2 * 2 + 1][0] = r[2]; bf[j2 * 2 + 1][1] = r[3];
            }
#pragma unroll
            for (int i = 0; i < 4; i++)
#pragma unroll
                for (int j = 0; j < 4; j++)
                    mma16816(acc[i][j], aH[i], bf[j]);
        }
    }

    // epilogue: weighted atomic scatter-add (2 adds/elem total -> deterministic)
    int r0 = lane >> 2, cc = 2 * (lane & 3);
#pragma unroll
    for (int i = 0; i < 4; i++)
#pragma unroll
        for (int h = 0; h < 2; h++) {
            int row = row_start + wm + i * 16 + r0 + h * 8;
            int tok = g_row_token[row];
            if (tok < 0) continue;
            float w = g_row_weight[row];
            float* ob = out + (size_t)tok * HDIM + n0;
#pragma unroll
            for (int j = 0; j < 4; j++) {
                int col = wn + j * 8 + cc;
                atomicAdd(ob + col,     w * acc[i][j][2 * h]);
                atomicAdd(ob + col + 1, w * acc[i][j][2 * h + 1]);
            }
        }
#undef G2_ISSUE
}

// ---------------- launch -----------------------------------------------------
extern "C" void kernel_launch(void* const* d_in, const int* in_sizes, int n_in,
                              void* d_out, int out_size) {
    const float* x  = (const float*)d_in[0];
    const float* gw = (const float*)d_in[1];
    const float* w1 = (const float*)d_in[2];
    const float* w3 = (const float*)d_in[3];
    const float* w2 = (const float*)d_in[4];
    float* out = (float*)d_out;

    static int attr_done = 0;
    if (!attr_done) {
        cudaFuncSetAttribute(gemm1_kernel, cudaFuncAttributeMaxDynamicSharedMemorySize, NSTG * STAGE);
        cudaFuncSetAttribute(gemm2_kernel, cudaFuncAttributeMaxDynamicSharedMemorySize, NSTG * STAGE);
        attr_done = 1;
    }

    reset_kernel<<<(T_TOK * HDIM + 255) / 256, 256>>>(out);
    router_kernel<<<T_TOK, 256>>>(x, gw);
    plan_kernel<<<1, 32>>>();
    scatter_kernel<<<(T_TOK + 255) / 256, 256>>>();
    prep_w_kernel<<<dim3(32768, 3), 256>>>(w1, w3, w2);
    prep_x_kernel<<<4096, 256>>>(x);   // 4096*256*4 = 4,194,304 = T_TOK*HDIM  (R11 bug: was 2048)

    gemm1_kernel<<<dim3(32, MAX_TILES), 256, NSTG * STAGE>>>();
    gemm2_kernel<<<dim3(16, MAX_TILES), 256, NSTG * STAGE>>>(out);
}

// round 14
// speedup vs baseline: 5.2276x; 1.0417x over previous
#include <cuda_runtime.h>
#include <cuda_fp16.h>
#include <cstdint>

#define T_TOK 2048
#define HDIM  2048
#define IDIM  2048
#define NEXP  8
#define ROWS_PAD 5120          // 40 tiles * 128
#define MAX_TILES 40
#define WMAT ((size_t)2048 * 2048)

// both GEMM stages: A 0..10239 (128 rows * 80B), B at 10240..18431
#define APITCH 80
#define BOFF   10240
#define STAGE  18432
#define NSTG   5

// ---------------- device scratch ---------------------------------------------
__device__ __half   g_w1h[NEXP * WMAT];   // fp16 weights, same [E][K][N] layout
__device__ __half   g_w3h[NEXP * WMAT];
__device__ __half   g_w2h[NEXP * WMAT];
__device__ __half   g_xh[(size_t)T_TOK * HDIM];     // x fp16
__device__ __half   g_acth[(size_t)ROWS_PAD * IDIM]; // silu(g)*u fp16
__device__ int   g_row_token[ROWS_PAD];
__device__ float g_row_weight[ROWS_PAD];
__device__ int   g_tok_e[2 * T_TOK];
__device__ float g_tok_w[2 * T_TOK];
__device__ int   g_counts[NEXP];
__device__ int   g_cursor[NEXP];
__device__ int   g_seg_start[NEXP];
__device__ int   g_tile_e[MAX_TILES];
__device__ int   g_tile_row[MAX_TILES];

// ---------------- helpers ----------------------------------------------------
__device__ __forceinline__ uint32_t smem_u32(const void* p) {
    return (uint32_t)__cvta_generic_to_shared(p);
}
__device__ __forceinline__ void mma16816(float* c, const uint32_t* a, const uint32_t* b) {
    asm volatile(
        "mma.sync.aligned.m16n8k16.row.col.f32.f16.f16.f32 "
        "{%0,%1,%2,%3}, {%4,%5,%6,%7}, {%8,%9}, {%0,%1,%2,%3};"
        : "+f"(c[0]), "+f"(c[1]), "+f"(c[2]), "+f"(c[3])
        : "r"(a[0]), "r"(a[1]), "r"(a[2]), "r"(a[3]), "r"(b[0]), "r"(b[1]));
}
__device__ __forceinline__ void ldsm4(uint32_t* r, uint32_t a) {
    asm volatile("ldmatrix.sync.aligned.m8n8.x4.shared.b16 {%0,%1,%2,%3}, [%4];"
        : "=r"(r[0]), "=r"(r[1]), "=r"(r[2]), "=r"(r[3]) : "r"(a));
}
__device__ __forceinline__ void ldsm4t(uint32_t* r, uint32_t a) {
    asm volatile("ldmatrix.sync.aligned.m8n8.x4.trans.shared.b16 {%0,%1,%2,%3}, [%4];"
        : "=r"(r[0]), "=r"(r[1]), "=r"(r[2]), "=r"(r[3]) : "r"(a));
}
// cp.async 16B; n = src bytes (0 -> zero-fill)
__device__ __forceinline__ void cpa16(uint32_t d, const void* s, uint32_t n) {
    asm volatile("cp.async.cg.shared.global [%0], [%1], 16, %2;"
                 :: "r"(d), "l"(s), "r"(n) : "memory");
}
__device__ __forceinline__ void cpa16(uint32_t d, const void* s) {
    asm volatile("cp.async.cg.shared.global [%0], [%1], 16;"
                 :: "r"(d), "l"(s) : "memory");
}
#define CP_COMMIT() asm volatile("cp.async.commit_group;" ::: "memory")
// wait so that chunk c is complete; issued max = min(c+3, 63)
#define CP_WAIT_FOR(c) do {                                                       \
        if      ((c) <= 60) asm volatile("cp.async.wait_group 3;" ::: "memory");  \
        else if ((c) == 61) asm volatile("cp.async.wait_group 2;" ::: "memory");  \
        else if ((c) == 62) asm volatile("cp.async.wait_group 1;" ::: "memory");  \
        else                asm volatile("cp.async.wait_group 0;" ::: "memory");  \
    } while (0)
__device__ __forceinline__ uint32_t cvt2(float a, float b) {
    __half2 h = __floats2half2_rn(a, b);
    return *(uint32_t*)&h;
}

// ---------------- reset ------------------------------------------------------
__global__ void reset_kernel(float* __restrict__ out) {
    int idx = blockIdx.x * 256 + threadIdx.x;
    if (idx < T_TOK * HDIM) out[idx] = 0.0f;
    if (idx < ROWS_PAD) g_row_token[idx] = -1;
    if (idx < NEXP) { g_counts[idx] = 0; g_cursor[idx] = 0; }
}

// ---------------- router -----------------------------------------------------
__global__ __launch_bounds__(256) void router_kernel(const float* __restrict__ x,
                                                     const float* __restrict__ gw) {
    int t = blockIdx.x;
    const float* xr = x + (size_t)t * HDIM;
    float acc[NEXP];
#pragma unroll
    for (int e = 0; e < NEXP; e++) acc[e] = 0.0f;
    for (int h = threadIdx.x; h < HDIM; h += 256) {
        float xv = xr[h];
#pragma unroll
        for (int e = 0; e < NEXP; e++) acc[e] = fmaf(xv, gw[e * HDIM + h], acc[e]);
    }
#pragma unroll
    for (int off = 16; off > 0; off >>= 1)
#pragma unroll
        for (int e = 0; e < NEXP; e++)
            acc[e] += __shfl_down_sync(0xffffffffu, acc[e], off);

    __shared__ float red[8][NEXP];
    int wid = threadIdx.x >> 5, lane = threadIdx.x & 31;
    if (lane == 0)
#pragma unroll
        for (int e = 0; e < NEXP; e++) red[wid][e] = acc[e];
    __syncthreads();

    if (threadIdx.x == 0) {
        float l[NEXP];
#pragma unroll
        for (int e = 0; e < NEXP; e++) {
            float s = 0.0f;
#pragma unroll
            for (int w = 0; w < 8; w++) s += red[w][e];
            l[e] = s;
        }
        int i0 = 0;
#pragma unroll
        for (int e = 1; e < NEXP; e++) if (l[e] > l[i0]) i0 = e;
        int i1 = -1;
#pragma unroll
        for (int e = 0; e < NEXP; e++)
            if (e != i0 && (i1 < 0 || l[e] > l[i1])) i1 = e;
        float w0 = 1.0f / (1.0f + expf(l[i1] - l[i0]));
        float w1 = 1.0f - w0;
        g_tok_e[2 * t] = i0;     g_tok_e[2 * t + 1] = i1;
        g_tok_w[2 * t] = w0;     g_tok_w[2 * t + 1] = w1;
        atomicAdd(&g_counts[i0], 1);
        atomicAdd(&g_counts[i1], 1);
    }
}

// ---------------- plan + scatter ---------------------------------------------
__global__ void plan_kernel() {
    if (threadIdx.x != 0) return;
    int off = 0, tile = 0;
    for (int e = 0; e < NEXP; e++) {
        g_seg_start[e] = off;
        int n = g_counts[e];
        int nt = (n + 127) >> 7;
        for (int j = 0; j < nt; j++) { g_tile_e[tile] = e; g_tile_row[tile] = off + (j << 7); tile++; }
        off += nt << 7;
    }
    for (; tile < MAX_TILES; tile++) g_tile_e[tile] = -1;
}

__global__ void scatter_kernel() {
    int t = blockIdx.x * 256 + threadIdx.x;
    if (t >= T_TOK) return;
#pragma unroll
    for (int k = 0; k < 2; k++) {
        int e = g_tok_e[2 * t + k];
        int r = atomicAdd(&g_cursor[e], 1);
        int row = g_seg_start[e] + r;
        g_row_token[row] = t;
        g_row_weight[row] = g_tok_w[2 * t + k];
    }
}

// ---------------- prep: weights + x fp32 -> fp16 -----------------------------
__global__ __launch_bounds__(256) void prep_w_kernel(const float* __restrict__ w1,
                                                     const float* __restrict__ w3,
                                                     const float* __restrict__ w2) {
    int mat = blockIdx.y;
    const float* src = (mat == 0 ? w1 : (mat == 1 ? w3 : w2));
    __half* dst = (mat == 0 ? g_w1h : (mat == 1 ? g_w3h : g_w2h));
    size_t i = ((size_t)blockIdx.x * 256 + threadIdx.x);
    float4 v = *(const float4*)(src + 4 * i);
    uint2 o;
    o.x = cvt2(v.x, v.y);
    o.y = cvt2(v.z, v.w);
    *(uint2*)(dst + 4 * i) = o;
}

__global__ __launch_bounds__(256) void prep_x_kernel(const float* __restrict__ x) {
    size_t i = ((size_t)blockIdx.x * 256 + threadIdx.x);
    float4 v = *(const float4*)(x + 4 * i);
    uint2 hi;
    hi.x = cvt2(v.x, v.y);
    hi.y = cvt2(v.z, v.w);
    *(uint2*)(g_xh + 4 * i) = hi;
}

// ---------------- GEMM1: HMMA fp16, fused gate+up + SiLU, 5-stage pipe -------
// CTA: M=128, N=64 (per mat), KC=32. 8 warps = 4(M) x 2(N), warp 32x32, dual acc.
__global__ __launch_bounds__(256, 2) void gemm1_kernel() {
    int e = g_tile_e[blockIdx.y];
    if (e < 0) return;
    int row_start = g_tile_row[blockIdx.y];
    int n0 = blockIdx.x * 64;
    extern __shared__ __align__(1024) char smem[];
    uint32_t SB = smem_u32(smem);

    const int tid = threadIdx.x;
    const int lane = tid & 31, wid = tid >> 5;
    const int wm = (wid & 3) * 32, wn = (wid >> 2) * 32;

    // staging maps
    const int bmat = tid >> 7;                  // 0:w1  1:w3
    const int bk = (tid & 127) >> 2;            // 0..31
    const int bn = (tid & 3) * 16;              // half col offset
    const __half* bsrc = (bmat ? g_w3h : g_w1h) + (size_t)e * WMAT + (size_t)bk * IDIM + n0 + bn;
    const int ar = tid >> 1;                    // 0..127
    const int akh = (tid & 1) * 16;             // K elems
    int tok0 = g_row_token[row_start + ar];
    const uint32_t asz = (tok0 >= 0) ? 16u : 0u;
    const __half* axh = (tok0 >= 0) ? g_xh + (size_t)tok0 * HDIM + akh : g_xh;

    const uint32_t a_sts = (uint32_t)(ar * APITCH + akh * 2);
    const uint32_t bswz = (uint32_t)((bk & 7) * 16);
    const uint32_t b_base = (uint32_t)(BOFF + bmat * 4096 + bk * 128);
    const uint32_t b_sts0 = b_base + (((uint32_t)(bn * 2)) ^ bswz);
    const uint32_t b_sts1 = b_base + (((uint32_t)(bn * 2 + 16)) ^ bswz);

    float accG[2][4][4], accU[2][4][4];
#pragma unroll
    for (int i = 0; i < 2; i++)
#pragma unroll
        for (int j = 0; j < 4; j++)
#pragma unroll
            for (int q = 0; q < 4; q++) { accG[i][j][q] = 0.0f; accU[i][j][q] = 0.0f; }

#define G1_ISSUE(ch, slot) do {                                                   \
        uint32_t stb = SB + (uint32_t)(slot) * STAGE;                             \
        int k0 = (ch) * 32;                                                       \
        cpa16(stb + a_sts,      axh + k0,     asz);                               \
        cpa16(stb + a_sts + 16, axh + k0 + 8, asz);                               \
        const __half* bp = bsrc + (size_t)k0 * IDIM;                              \
        cpa16(stb + b_sts0, bp);                                                  \
        cpa16(stb + b_sts1, bp + 8);                                              \
        CP_COMMIT();                                                              \
    } while (0)

    G1_ISSUE(0, 0);
    G1_ISSUE(1, 1);
    G1_ISSUE(2, 2);

    for (int c = 0; c < 64; c++) {
        if (c + 3 < 64) G1_ISSUE(c + 3, (c + 3) % NSTG);
        CP_WAIT_FOR(c);
        __syncthreads();

        uint32_t stb = SB + (uint32_t)(c % NSTG) * STAGE;
#pragma unroll
        for (int s = 0; s < 2; s++) {
            uint32_t aH[2][4];
#pragma unroll
            for (int i = 0; i < 2; i++) {
                uint32_t ab = stb + (uint32_t)((wm + i * 16 + (lane & 15)) * APITCH +
                                               ((lane >> 4) * 16) + s * 32);
                ldsm4(aH[i], ab);
            }
            int krow = s * 16 + (lane & 15);
            uint32_t ksw = (uint32_t)((krow & 7) * 16);
            uint32_t rowb = (uint32_t)(krow * 128);
            uint32_t bf[2][4][2];
#pragma unroll
            for (int m = 0; m < 2; m++)
#pragma unroll
                for (int j2 = 0; j2 < 2; j2++) {
                    uint32_t chunk = (((uint32_t)((wn + j2 * 16) * 2 + (lane >> 4) * 16)) ^ ksw);
                    uint32_t r[4];
                    ldsm4t(r, stb + BOFF + (uint32_t)m * 4096 + rowb + chunk);
                    bf[m][j2 * 2][0] = r[0]; bf[m][j2 * 2][1] = r[1];
                    bf[m][j2 * 2 + 1][0] = r[2]; bf[m][j2 * 2 + 1][1] = r[3];
                }
#pragma unroll
            for (int i = 0; i < 2; i++)
#pragma unroll
                for (int j = 0; j < 4; j++) {
                    mma16816(accG[i][j], aH[i], bf[0][j]);
                    mma16816(accU[i][j], aH[i], bf[1][j]);
                }
        }
    }

    // epilogue: silu(G)*U -> g_acth (fp16)
    int r0 = lane >> 2, cc = 2 * (lane & 3);
#pragma unroll
    for (int i = 0; i < 2; i++)
#pragma unroll
        for (int j = 0; j < 4; j++) {
            int col = n0 + wn + j * 8 + cc;
#pragma unroll
            for (int h = 0; h < 2; h++) {
                int row = row_start + wm + i * 16 + r0 + h * 8;
                float g0 = accG[i][j][2 * h],     u0 = accU[i][j][2 * h];
                float g1 = accG[i][j][2 * h + 1], u1 = accU[i][j][2 * h + 1];
                float a0 = (g0 / (1.0f + __expf(-g0))) * u0;
                float a1 = (g1 / (1.0f + __expf(-g1))) * u1;
                *(uint32_t*)&g_acth[(size_t)row * IDIM + col] = cvt2(a0, a1);
            }
        }
#undef G1_ISSUE
}

// ---------------- GEMM2: HMMA fp16, down proj + weighted scatter, 5-stage ----
// CTA: M=128, N=128, KC=32. 8 warps = 2(M) x 4(N), warp 64x32. 2 CTAs/SM.
__global__ __launch_bounds__(256, 2) void gemm2_kernel(float* __restrict__ out) {
    int e = g_tile_e[blockIdx.y];
    if (e < 0) return;
    int row_start = g_tile_row[blockIdx.y];
    int n0 = blockIdx.x * 128;
    extern __shared__ __align__(1024) char smem[];
    uint32_t SB = smem_u32(smem);

    const int tid = threadIdx.x;
    const int lane = tid & 31, wid = tid >> 5;
    const int wm = (wid & 1) * 64, wn = (wid >> 1) * 32;

    const int ar = tid >> 1;
    const int akh = (tid & 1) * 16;             // halfs
    const __half* asrc = g_acth + (size_t)(row_start + ar) * IDIM + akh;
    const int bk = tid >> 3;                    // 0..31
    const int bn = (tid & 7) * 16;              // halfs
    const __half* bsrc = g_w2h + (size_t)e * WMAT + (size_t)bk * HDIM + n0 + bn;

    const uint32_t a_sts = (uint32_t)(ar * APITCH + akh * 2);
    const uint32_t bswz = (uint32_t)((bk & 7) * 16);
    const uint32_t b_base = (uint32_t)(BOFF + bk * 256);
    const uint32_t b_sts0 = b_base + (((uint32_t)(bn * 2)) ^ bswz);
    const uint32_t b_sts1 = b_base + (((uint32_t)(bn * 2 + 16)) ^ bswz);

    float acc[4][4][4];
#pragma unroll
    for (int i = 0; i < 4; i++)
#pragma unroll
        for (int j = 0; j < 4; j++)
#pragma unroll
            for (int q = 0; q < 4; q++) acc[i][j][q] = 0.0f;

#define G2_ISSUE(ch, slot) do {                                                   \
        uint32_t stb = SB + (uint32_t)(slot) * STAGE;                             \
        int k0 = (ch) * 32;                                                       \
        cpa16(stb + a_sts,      asrc + k0);                                       \
        cpa16(stb + a_sts + 16, asrc + k0 + 8);                                   \
        const __half* bp = bsrc + (size_t)k0 * HDIM;                              \
        cpa16(stb + b_sts0, bp);                                                  \
        cpa16(stb + b_sts1, bp + 8);                                              \
        CP_COMMIT();                                                              \
    } while (0)

    G2_ISSUE(0, 0);
    G2_ISSUE(1, 1);
    G2_ISSUE(2, 2);

    for (int c = 0; c < 64; c++) {
        if (c + 3 < 64) G2_ISSUE(c + 3, (c + 3) % NSTG);
        CP_WAIT_FOR(c);
        __syncthreads();

        uint32_t stb = SB + (uint32_t)(c % NSTG) * STAGE;
#pragma unroll
        for (int s = 0; s < 2; s++) {
            uint32_t aH[4][4];
#pragma unroll
            for (int i = 0; i < 4; i++) {
                uint32_t ab = stb + (uint32_t)((wm + i * 16 + (lane & 15)) * APITCH +
                                               ((lane >> 4) * 16) + s * 32);
                ldsm4(aH[i], ab);
            }
            int krow = s * 16 + (lane & 15);
            uint32_t ksw = (uint32_t)((krow & 7) * 16);
            uint32_t rowb = (uint32_t)(krow * 256);
            uint32_t bf[4][2];
#pragma unroll
            for (int j2 = 0; j2 < 2; j2++) {
                uint32_t chunk = (((uint32_t)((wn + j2 * 16) * 2 + (lane >> 4) * 16)) ^ ksw);
                uint32_t r[4];
                ldsm4t(r, stb + BOFF + rowb + chunk);
                bf[j2 * 2][0] = r[0]; bf[j2 * 2][1] = r[1];
                bf[j2 * 2 + 1][0] = r[2]; bf[j2 * 2 + 1][1] = r[3];
            }
#pragma unroll
            for (int i = 0; i < 4; i++)
#pragma unroll
                for (int j = 0; j < 4; j++)
                    mma16816(acc[i][j], aH[i], bf[j]);
        }
    }

    // epilogue: weighted atomic scatter-add (2 adds/elem total -> deterministic)
    int r0 = lane >> 2, cc = 2 * (lane & 3);
#pragma unroll
    for (int i = 0; i < 4; i++)
#pragma unroll
        for (int h = 0; h < 2; h++) {
            int row = row_start + wm + i * 16 + r0 + h * 8;
            int tok = g_row_token[row];
            if (tok < 0) continue;
            float w = g_row_weight[row];
            float* ob = out + (size_t)tok * HDIM + n0;
#pragma unroll
            for (int j = 0; j < 4; j++) {
                int col = wn + j * 8 + cc;
                atomicAdd(ob + col,     w * acc[i][j][2 * h]);
                atomicAdd(ob + col + 1, w * acc[i][j][2 * h + 1]);
            }
        }
#undef G2_ISSUE
}

// ---------------- launch -----------------------------------------------------
extern "C" void kernel_launch(void* const* d_in, const int* in_sizes, int n_in,
                              void* d_out, int out_size) {
    const float* x  = (const float*)d_in[0];
    const float* gw = (const float*)d_in[1];
    const float* w1 = (const float*)d_in[2];
    const float* w3 = (const float*)d_in[3];
    const float* w2 = (const float*)d_in[4];
    float* out = (float*)d_out;

    cudaFuncSetAttribute(gemm1_kernel, cudaFuncAttributeMaxDynamicSharedMemorySize, NSTG * STAGE);
    cudaFuncSetAttribute(gemm2_kernel, cudaFuncAttributeMaxDynamicSharedMemorySize, NSTG * STAGE);

    reset_kernel<<<(T_TOK * HDIM + 255) / 256, 256>>>(out);
    router_kernel<<<T_TOK, 256>>>(x, gw);
    plan_kernel<<<1, 32>>>();
    scatter_kernel<<<(T_TOK + 255) / 256, 256>>>();
    prep_w_kernel<<<dim3(32768, 3), 256>>>(w1, w3, w2);
    prep_x_kernel<<<4096, 256>>>(x);

    gemm1_kernel<<<dim3(32, MAX_TILES), 256, NSTG * STAGE>>>();
    gemm2_kernel<<<dim3(16, MAX_TILES), 256, NSTG * STAGE>>>(out);
}